// round 2
// baseline (speedup 1.0000x reference)
#include <cuda_runtime.h>
#include <math.h>

#define NN 4096
#define DD 256

// ---------------- scratch (device globals; no allocation) ----------------
__device__ float g_h0[NN * DD];
__device__ float g_sim[NN * NN];        // 64 MB
__device__ int   g_idx[NN * 16];
__device__ float g_x[NN * DD];
__device__ float g_y[NN * DD];
__device__ float g_t[NN * DD];
__device__ float g_qkv[NN * 768];
__device__ float g_ff[NN * 512];
__device__ float g_ssrc[NN * 4];
__device__ float g_sdst[NN * 4];

// ---------------- GEMM: C[M,N] = act(A[M,K] @ B (+bias)) ----------------
// BT=false: B is [K,N].  BT=true: B is [N,K] (C = A @ B^T).
// ACT: 0=none 1=relu 2=tanh
template<bool BT, int ACT>
__global__ void __launch_bounds__(256) gemm_k(const float* __restrict__ A,
                                              const float* __restrict__ B,
                                              const float* __restrict__ bias,
                                              float* __restrict__ C,
                                              int M, int N, int K)
{
    __shared__ float As[16][132];   // As[k][m], padded
    __shared__ float Bs[16][68];    // Bs[k][n], padded
    const int tid = threadIdx.x;
    const int tx = tid & 15, ty = tid >> 4;
    const int bm = blockIdx.y * 128, bn = blockIdx.x * 64;

    float acc[8][4];
#pragma unroll
    for (int i = 0; i < 8; i++)
#pragma unroll
        for (int j = 0; j < 4; j++) acc[i][j] = 0.f;

    for (int k0 = 0; k0 < K; k0 += 16) {
        {   // A tile 128x16, stored transposed
            int r = tid >> 2, c = (tid & 3) << 2;
#pragma unroll
            for (int p = 0; p < 2; p++) {
                float4 v = *(const float4*)&A[(long)(bm + r + p * 64) * K + k0 + c];
                As[c + 0][r + p * 64] = v.x; As[c + 1][r + p * 64] = v.y;
                As[c + 2][r + p * 64] = v.z; As[c + 3][r + p * 64] = v.w;
            }
        }
        if (!BT) {
            int r = tid >> 4, c = (tid & 15) << 2;   // 16 x 64
            float4 v = *(const float4*)&B[(long)(k0 + r) * N + bn + c];
            *(float4*)&Bs[r][c] = v;
        } else {
            int r = tid >> 2, c = (tid & 3) << 2;    // 64 n-rows x 16 k-cols
            float4 v = *(const float4*)&B[(long)(bn + r) * K + k0 + c];
            Bs[c + 0][r] = v.x; Bs[c + 1][r] = v.y;
            Bs[c + 2][r] = v.z; Bs[c + 3][r] = v.w;
        }
        __syncthreads();
#pragma unroll
        for (int kk = 0; kk < 16; kk++) {
            float a[8], b[4];
            *(float4*)&a[0] = *(const float4*)&As[kk][ty * 8];
            *(float4*)&a[4] = *(const float4*)&As[kk][ty * 8 + 4];
            *(float4*)&b[0] = *(const float4*)&Bs[kk][tx * 4];
#pragma unroll
            for (int i = 0; i < 8; i++)
#pragma unroll
                for (int j = 0; j < 4; j++)
                    acc[i][j] = fmaf(a[i], b[j], acc[i][j]);
        }
        __syncthreads();
    }
#pragma unroll
    for (int i = 0; i < 8; i++) {
        int row = bm + ty * 8 + i;
#pragma unroll
        for (int j = 0; j < 4; j++) {
            int col = bn + tx * 4 + j;
            float v = acc[i][j];
            if (bias) v += bias[col];
            if (ACT == 1) v = fmaxf(v, 0.f);
            if (ACT == 2) v = tanhf(v);
            C[(long)row * N + col] = v;
        }
    }
}

// ---------------- top-16 per row (relu + diag mask, lowest-index ties) ----
__global__ void __launch_bounds__(256) topk_kernel(const float* __restrict__ sim,
                                                   int* __restrict__ idx)
{
    const int row = blockIdx.x, t = threadIdx.x;
    float lv[16];
#pragma unroll
    for (int i = 0; i < 16; i++) {
        int j = i * 256 + t;
        float v = sim[(long)row * NN + j];
        v = fmaxf(v, 0.f);           // relu
        if (j == row) v = -1e9f;     // mask self
        lv[i] = v;
    }
    __shared__ float sv[256];
    __shared__ int   si[256];
    for (int r = 0; r < 16; r++) {
        float bv = -2e9f; int bi = 0;
#pragma unroll
        for (int i = 0; i < 16; i++) {          // j ascending -> '>' keeps smallest idx
            if (lv[i] > bv) { bv = lv[i]; bi = i * 256 + t; }
        }
        sv[t] = bv; si[t] = bi;
        __syncthreads();
        for (int s = 128; s > 0; s >>= 1) {
            if (t < s) {
                if (sv[t + s] > sv[t] || (sv[t + s] == sv[t] && si[t + s] < si[t])) {
                    sv[t] = sv[t + s]; si[t] = si[t + s];
                }
            }
            __syncthreads();
        }
        int winj = si[0];
        if (t == 0) idx[row * 16 + r] = winj;
        if ((winj & 255) == t) lv[winj >> 8] = -2e9f;
        __syncthreads();
    }
}

// ---------------- GAT per-node attention scores ---------------------------
__global__ void __launch_bounds__(256) gat_scores(const float* __restrict__ h,
                                                  const float* __restrict__ a_s,
                                                  const float* __restrict__ a_d,
                                                  float* __restrict__ ssrc,
                                                  float* __restrict__ sdst,
                                                  int heads)
{
    const int n = blockIdx.x, t = threadIdx.x;
    float hv = h[(long)n * 256 + t];
    float ps = hv * a_s[t];
    float pd = hv * a_d[t];
#pragma unroll
    for (int m = 16; m; m >>= 1) {
        ps += __shfl_xor_sync(0xffffffffu, ps, m);
        pd += __shfl_xor_sync(0xffffffffu, pd, m);
    }
    __shared__ float ws[8], wd[8];
    if ((t & 31) == 0) { ws[t >> 5] = ps; wd[t >> 5] = pd; }
    __syncthreads();
    if (t < heads) {
        int wph = 8 / heads;
        float s = 0.f, d = 0.f;
        for (int w = 0; w < wph; w++) { s += ws[t * wph + w]; d += wd[t * wph + w]; }
        ssrc[n * heads + t] = s;
        sdst[n * heads + t] = d;
    }
}

// ---------------- GAT aggregation (17 in-edges per dst) -------------------
template<int HEADS>
__global__ void __launch_bounds__(256) gat_agg(const float* __restrict__ h,
                                               const float* __restrict__ ssrc,
                                               const float* __restrict__ sdst,
                                               const int* __restrict__ idx,
                                               const float* __restrict__ bias,
                                               float* __restrict__ out,
                                               int do_relu)
{
    const int i = blockIdx.x, t = threadIdx.x;
    __shared__ int   s_src[17];
    __shared__ float s_e[HEADS * 17];
    __shared__ float s_a[HEADS * 17];
    if (t < 16) s_src[t] = idx[i * 16 + t];
    if (t == 16) s_src[16] = i;
    __syncthreads();
    if (t < HEADS * 17) {
        int hh = t / 17, j = t % 17;
        float e = ssrc[s_src[j] * HEADS + hh] + sdst[i * HEADS + hh];
        s_e[t] = e > 0.f ? e : 0.2f * e;   // leaky_relu(0.2)
    }
    __syncthreads();
    if (t < HEADS) {
        float m = -1e30f;
        for (int j = 0; j < 17; j++) m = fmaxf(m, s_e[t * 17 + j]);
        float s = 0.f;
        for (int j = 0; j < 17; j++) {
            float p = __expf(s_e[t * 17 + j] - m);
            s_a[t * 17 + j] = p; s += p;
        }
        float inv = 1.f / s;
        for (int j = 0; j < 17; j++) s_a[t * 17 + j] *= inv;
    }
    __syncthreads();
    const int hh = t / (256 / HEADS);
    float acc = 0.f;
#pragma unroll
    for (int j = 0; j < 17; j++)
        acc = fmaf(s_a[hh * 17 + j], h[(long)s_src[j] * 256 + t], acc);
    float o = acc + bias[t];
    if (do_relu) o = fmaxf(o, 0.f);
    out[(long)i * 256 + t] = o;
}

// ---------------- flash attention (4 heads, dh=64, N=4096) ----------------
__global__ void __launch_bounds__(256) attn_kernel(const float* __restrict__ qkv,
                                                   float* __restrict__ out)
{
    __shared__ float Qt[64][68];  // Qt[d][q]  (scaled)
    __shared__ float Kt[64][36];  // Kt[d][key]
    __shared__ float Vs[32][68];  // Vs[key][d]
    __shared__ float Pt[32][68];  // Pt[key][q]
    const int tid = threadIdx.x;
    const int tx = tid & 15, ty = tid >> 4;
    const int q0 = blockIdx.x * 64;
    const int hh = blockIdx.y;
    {
        int r = tid >> 4, c = (tid & 15) << 2;
#pragma unroll
        for (int p = 0; p < 4; p++) {
            float4 v = *(const float4*)&qkv[(long)(q0 + r + p * 16) * 768 + hh * 64 + c];
            Qt[c + 0][r + p * 16] = v.x * 0.125f; Qt[c + 1][r + p * 16] = v.y * 0.125f;
            Qt[c + 2][r + p * 16] = v.z * 0.125f; Qt[c + 3][r + p * 16] = v.w * 0.125f;
        }
    }
    float acc[4][4];
#pragma unroll
    for (int i = 0; i < 4; i++)
#pragma unroll
        for (int j = 0; j < 4; j++) acc[i][j] = 0.f;
    float mrow[4] = {-1e30f, -1e30f, -1e30f, -1e30f};
    float lrow[4] = {0.f, 0.f, 0.f, 0.f};

    for (int kt = 0; kt < 128; kt++) {
        __syncthreads();   // prior PV done before K/V/P overwrite
        {
            int r = tid >> 4, c = (tid & 15) << 2;
#pragma unroll
            for (int p = 0; p < 2; p++) {
                long base = (long)(kt * 32 + r + p * 16) * 768 + hh * 64 + c;
                float4 kv = *(const float4*)&qkv[base + 256];
                Kt[c + 0][r + p * 16] = kv.x; Kt[c + 1][r + p * 16] = kv.y;
                Kt[c + 2][r + p * 16] = kv.z; Kt[c + 3][r + p * 16] = kv.w;
                float4 vv = *(const float4*)&qkv[base + 512];
                *(float4*)&Vs[r + p * 16][c] = vv;
            }
        }
        __syncthreads();
        float s[4][2];
#pragma unroll
        for (int i = 0; i < 4; i++) { s[i][0] = 0.f; s[i][1] = 0.f; }
#pragma unroll 8
        for (int kk = 0; kk < 64; kk++) {
            float4 a = *(const float4*)&Qt[kk][ty << 2];
            float b0 = Kt[kk][tx * 2], b1 = Kt[kk][tx * 2 + 1];
            s[0][0] = fmaf(a.x, b0, s[0][0]); s[0][1] = fmaf(a.x, b1, s[0][1]);
            s[1][0] = fmaf(a.y, b0, s[1][0]); s[1][1] = fmaf(a.y, b1, s[1][1]);
            s[2][0] = fmaf(a.z, b0, s[2][0]); s[2][1] = fmaf(a.z, b1, s[2][1]);
            s[3][0] = fmaf(a.w, b0, s[3][0]); s[3][1] = fmaf(a.w, b1, s[3][1]);
        }
#pragma unroll
        for (int i = 0; i < 4; i++) {
            float tm = fmaxf(s[i][0], s[i][1]);
#pragma unroll
            for (int m = 8; m; m >>= 1) tm = fmaxf(tm, __shfl_xor_sync(0xffffffffu, tm, m));
            float mnew = fmaxf(mrow[i], tm);
            float p0 = __expf(s[i][0] - mnew), p1 = __expf(s[i][1] - mnew);
            float ps = p0 + p1;
#pragma unroll
            for (int m = 8; m; m >>= 1) ps += __shfl_xor_sync(0xffffffffu, ps, m);
            float corr = __expf(mrow[i] - mnew);
            lrow[i] = lrow[i] * corr + ps;
            mrow[i] = mnew;
            acc[i][0] *= corr; acc[i][1] *= corr; acc[i][2] *= corr; acc[i][3] *= corr;
            Pt[tx * 2][(ty << 2) + i]     = p0;
            Pt[tx * 2 + 1][(ty << 2) + i] = p1;
        }
        __syncthreads();
#pragma unroll 8
        for (int kk = 0; kk < 32; kk++) {
            float4 pv = *(const float4*)&Pt[kk][ty << 2];
            float4 vv = *(const float4*)&Vs[kk][tx << 2];
            acc[0][0] = fmaf(pv.x, vv.x, acc[0][0]); acc[0][1] = fmaf(pv.x, vv.y, acc[0][1]);
            acc[0][2] = fmaf(pv.x, vv.z, acc[0][2]); acc[0][3] = fmaf(pv.x, vv.w, acc[0][3]);
            acc[1][0] = fmaf(pv.y, vv.x, acc[1][0]); acc[1][1] = fmaf(pv.y, vv.y, acc[1][1]);
            acc[1][2] = fmaf(pv.y, vv.z, acc[1][2]); acc[1][3] = fmaf(pv.y, vv.w, acc[1][3]);
            acc[2][0] = fmaf(pv.z, vv.x, acc[2][0]); acc[2][1] = fmaf(pv.z, vv.y, acc[2][1]);
            acc[2][2] = fmaf(pv.z, vv.z, acc[2][2]); acc[2][3] = fmaf(pv.z, vv.w, acc[2][3]);
            acc[3][0] = fmaf(pv.w, vv.x, acc[3][0]); acc[3][1] = fmaf(pv.w, vv.y, acc[3][1]);
            acc[3][2] = fmaf(pv.w, vv.z, acc[3][2]); acc[3][3] = fmaf(pv.w, vv.w, acc[3][3]);
        }
    }
#pragma unroll
    for (int i = 0; i < 4; i++) {
        float inv = 1.f / lrow[i];
#pragma unroll
        for (int j = 0; j < 4; j++)
            out[(long)(q0 + (ty << 2) + i) * 256 + hh * 64 + (tx << 2) + j] = acc[i][j] * inv;
    }
}

// ---------------- residual + LayerNorm (row of 256) -----------------------
__global__ void __launch_bounds__(256) add_ln_kernel(const float* __restrict__ x,
                                                     const float* __restrict__ r,
                                                     const float* __restrict__ g,
                                                     const float* __restrict__ b,
                                                     float* __restrict__ out)
{
    const int n = blockIdx.x, t = threadIdx.x;
    float v = x[(long)n * 256 + t] + r[(long)n * 256 + t];
    __shared__ float red[8];
    float s = v;
#pragma unroll
    for (int m = 16; m; m >>= 1) s += __shfl_xor_sync(0xffffffffu, s, m);
    if ((t & 31) == 0) red[t >> 5] = s;
    __syncthreads();
    float tot = 0.f;
#pragma unroll
    for (int w = 0; w < 8; w++) tot += red[w];
    float mu = tot * (1.f / 256.f);
    float d = v - mu;
    float sq = d * d;
#pragma unroll
    for (int m = 16; m; m >>= 1) sq += __shfl_xor_sync(0xffffffffu, sq, m);
    __syncthreads();
    if ((t & 31) == 0) red[t >> 5] = sq;
    __syncthreads();
    float tv = 0.f;
#pragma unroll
    for (int w = 0; w < 8; w++) tv += red[w];
    float var = tv * (1.f / 256.f);
    out[(long)n * 256 + t] = d * rsqrtf(var + 1e-5f) * g[t] + b[t];
}

// ---------------- elementwise add (skip) ----------------------------------
__global__ void add_kernel(float* __restrict__ a, const float* __restrict__ b)
{
    long i = (long)blockIdx.x * 256 + threadIdx.x;
    a[i] += b[i];
}

// ---------------- transpose [4096,256] -> [256,4096] ----------------------
__global__ void transpose_kernel(const float* __restrict__ in, float* __restrict__ out)
{
    __shared__ float tile[32][33];
    const int bx = blockIdx.x * 32, by = blockIdx.y * 32;
    const int tx = threadIdx.x, ty = threadIdx.y;
#pragma unroll
    for (int p = 0; p < 4; p++)
        tile[ty + p * 8][tx] = in[(long)(by + ty + p * 8) * 256 + bx + tx];
    __syncthreads();
#pragma unroll
    for (int p = 0; p < 4; p++)
        out[(long)(bx + ty + p * 8) * 4096 + by + tx] = tile[tx][ty + p * 8];
}

// ---------------- launch ---------------------------------------------------
extern "C" void kernel_launch(void* const* d_in, const int* in_sizes, int n_in,
                              void* d_out, int out_size)
{
    const float* window   = (const float*)d_in[0];
    const float* gl_w     = (const float*)d_in[1];
    const float* gl_b     = (const float*)d_in[2];
    const float* enc_W    = (const float*)d_in[3];
    const float* enc_asrc = (const float*)d_in[4];
    const float* enc_adst = (const float*)d_in[5];
    const float* enc_b    = (const float*)d_in[6];
    const float* tr_wqkv  = (const float*)d_in[7];
    const float* tr_bqkv  = (const float*)d_in[8];
    const float* tr_wo    = (const float*)d_in[9];
    const float* tr_bo    = (const float*)d_in[10];
    const float* ln1g     = (const float*)d_in[11];
    const float* ln1b     = (const float*)d_in[12];
    const float* tr_w1    = (const float*)d_in[13];
    const float* tr_b1    = (const float*)d_in[14];
    const float* tr_w2    = (const float*)d_in[15];
    const float* tr_b2    = (const float*)d_in[16];
    const float* ln2g     = (const float*)d_in[17];
    const float* ln2b     = (const float*)d_in[18];
    const float* skip_w   = (const float*)d_in[19];
    const float* skip_b   = (const float*)d_in[20];
    const float* dec_W    = (const float*)d_in[21];
    const float* dec_asrc = (const float*)d_in[22];
    const float* dec_adst = (const float*)d_in[23];
    const float* dec_b    = (const float*)d_in[24];
    const float* dec_lW   = (const float*)d_in[25];
    const float* dec_lasrc= (const float*)d_in[26];
    const float* dec_ladst= (const float*)d_in[27];
    const float* dec_lb   = (const float*)d_in[28];

    float *h0, *simb, *xb, *yb, *tb, *qkvb, *ffb, *ssrc, *sdst;
    int* idxb;
    cudaGetSymbolAddress((void**)&h0,   g_h0);
    cudaGetSymbolAddress((void**)&simb, g_sim);
    cudaGetSymbolAddress((void**)&idxb, g_idx);
    cudaGetSymbolAddress((void**)&xb,   g_x);
    cudaGetSymbolAddress((void**)&yb,   g_y);
    cudaGetSymbolAddress((void**)&tb,   g_t);
    cudaGetSymbolAddress((void**)&qkvb, g_qkv);
    cudaGetSymbolAddress((void**)&ffb,  g_ff);
    cudaGetSymbolAddress((void**)&ssrc, g_ssrc);
    cudaGetSymbolAddress((void**)&sdst, g_sdst);

    dim3 blk(256);

    // graph learning: h0 = tanh(window @ gl_w + gl_b); sim = h0 @ h0^T; top-16
    gemm_k<false, 2><<<dim3(DD / 64, NN / 128), blk>>>(window, gl_w, gl_b, h0, NN, DD, DD);
    gemm_k<true, 0><<<dim3(NN / 64, NN / 128), blk>>>(h0, h0, nullptr, simb, NN, NN, DD);
    topk_kernel<<<NN, blk>>>(simb, idxb);

    // encoder: 3x GAT(4 heads) + relu
    const float* xin = window;
    for (int i = 0; i < 3; i++) {
        gemm_k<false, 0><<<dim3(4, 32), blk>>>(xin, enc_W + (long)i * DD * DD, nullptr, yb, NN, DD, DD);
        gat_scores<<<NN, blk>>>(yb, enc_asrc + i * 256, enc_adst + i * 256, ssrc, sdst, 4);
        gat_agg<4><<<NN, blk>>>(yb, ssrc, sdst, idxb, enc_b + i * DD, xb, 1);
        xin = xb;
    }

    // transformer bottleneck: 2 layers
    for (int i = 0; i < 2; i++) {
        gemm_k<true, 0><<<dim3(12, 32), blk>>>(xb, tr_wqkv + (long)i * 768 * DD, tr_bqkv + i * 768, qkvb, NN, 768, DD);
        attn_kernel<<<dim3(64, 4), blk>>>(qkvb, yb);
        gemm_k<true, 0><<<dim3(4, 32), blk>>>(yb, tr_wo + (long)i * DD * DD, tr_bo + i * DD, tb, NN, DD, DD);
        add_ln_kernel<<<NN, blk>>>(xb, tb, ln1g + i * DD, ln1b + i * DD, xb);
        gemm_k<false, 1><<<dim3(8, 32), blk>>>(xb, tr_w1 + (long)i * DD * 512, tr_b1 + i * 512, ffb, NN, 512, DD);
        gemm_k<false, 0><<<dim3(4, 32), blk>>>(ffb, tr_w2 + (long)i * 512 * DD, tr_b2 + i * DD, tb, NN, DD, 512);
        add_ln_kernel<<<NN, blk>>>(xb, tb, ln2g + i * DD, ln2b + i * DD, xb);
    }

    // skip connection
    gemm_k<false, 0><<<dim3(4, 32), blk>>>(window, skip_w, skip_b, tb, NN, DD, DD);
    add_kernel<<<NN, blk>>>(xb, tb);

    // decoder: 2x GAT(4 heads)+relu, then single-head GAT
    for (int i = 0; i < 2; i++) {
        gemm_k<false, 0><<<dim3(4, 32), blk>>>(xb, dec_W + (long)i * DD * DD, nullptr, yb, NN, DD, DD);
        gat_scores<<<NN, blk>>>(yb, dec_asrc + i * 256, dec_adst + i * 256, ssrc, sdst, 4);
        gat_agg<4><<<NN, blk>>>(yb, ssrc, sdst, idxb, dec_b + i * DD, xb, 1);
    }
    gemm_k<false, 0><<<dim3(4, 32), blk>>>(xb, dec_lW, nullptr, yb, NN, DD, DD);
    gat_scores<<<NN, blk>>>(yb, dec_lasrc, dec_ladst, ssrc, sdst, 1);
    gat_agg<1><<<NN, blk>>>(yb, ssrc, sdst, idxb, dec_lb, tb, 0);

    // output: transpose to [256, 4096]
    transpose_kernel<<<dim3(8, 128), dim3(32, 8)>>>(tb, (float*)d_out);
}

// round 5
// speedup vs baseline: 1.4622x; 1.4622x over previous
#include <cuda_runtime.h>
#include <cuda_bf16.h>
#include <math.h>
#include <stdint.h>

typedef __nv_bfloat16 bf16;

#define NN 4096
#define DD 256

// ---------------- scratch (device globals; no allocation) ----------------
__device__ bf16 g_win_h[NN * DD], g_win_l[NN * DD];
__device__ bf16 g_h0_h[NN * DD],  g_h0_l[NN * DD];
__device__ bf16 g_x_h[NN * DD],   g_x_l[NN * DD];
__device__ bf16 g_y_h[NN * DD],   g_y_l[NN * DD];
__device__ bf16 g_t_h[NN * DD],   g_t_l[NN * DD];
__device__ bf16 g_qkv_h[NN * 768], g_qkv_l[NN * 768];
__device__ bf16 g_ff_h[NN * 512],  g_ff_l[NN * 512];
__device__ bf16 g_vt_h[4 * 64 * NN], g_vt_l[4 * 64 * NN];
__device__ bf16 g_att_h[4L * NN * NN], g_att_l[4L * NN * NN];  // 128MB each
#define WPOOL 1572864
__device__ bf16 g_w_h[WPOOL], g_w_l[WPOOL];
__device__ float g_tb[NN * DD];
__device__ float g_ssrc[NN * 4], g_sdst[NN * 4];
__device__ int   g_idx[NN * 16];

// ---------------- helpers -------------------------------------------------
__device__ __forceinline__ void cp16(uint32_t dst, const void* src) {
    asm volatile("cp.async.cg.shared.global [%0], [%1], 16;" :: "r"(dst), "l"(src));
}
#define CP_COMMIT() asm volatile("cp.async.commit_group;")

__device__ __forceinline__ float rec(const bf16* H, const bf16* L, long i) {
    return __bfloat162float(H[i]) + __bfloat162float(L[i]);
}
__device__ __forceinline__ void split1(float v, bf16* H, bf16* L, long off) {
    bf16 h = __float2bfloat16(v);
    H[off] = h;
    L[off] = __float2bfloat16(v - __bfloat162float(h));
}
__device__ __forceinline__ uint32_t pk(bf16 a, bf16 b) {
    __nv_bfloat162 t = __halves2bfloat162(a, b);
    return *(uint32_t*)&t;
}
__device__ __forceinline__ void split2st(float v0, float v1, bf16* H, bf16* L, long off) {
    bf16 h0 = __float2bfloat16(v0), h1 = __float2bfloat16(v1);
    float r0 = v0 - __bfloat162float(h0), r1 = v1 - __bfloat162float(h1);
    *(uint32_t*)(H + off) = pk(h0, h1);
    *(uint32_t*)(L + off) = pk(__float2bfloat16(r0), __float2bfloat16(r1));
}
__device__ __forceinline__ void unp(uint32_t u, float& a, float& b) {
    __nv_bfloat162 t = *(__nv_bfloat162*)&u;
    a = __bfloat162float(t.x); b = __bfloat162float(t.y);
}

#define MMA_BF16(c, a, b0, b1) \
    asm volatile("mma.sync.aligned.m16n8k16.row.col.f32.bf16.bf16.f32 " \
                 "{%0,%1,%2,%3},{%4,%5,%6,%7},{%8,%9},{%0,%1,%2,%3};" \
                 : "+f"((c)[0]), "+f"((c)[1]), "+f"((c)[2]), "+f"((c)[3]) \
                 : "r"((a)[0]), "r"((a)[1]), "r"((a)[2]), "r"((a)[3]), \
                   "r"(b0), "r"(b1))

// ---------------- split-bf16 3-product GEMM (both operands k-major) -------
// C[M,N] = act(alpha * A @ B^T (+bias)); A[M,K], B[N,K]; all dual-plane bf16.
// BM=128 fixed; z batch via element strides. ACT: 0 none, 1 relu, 2 tanh.
template<int BN, int ACT>
__global__ void __launch_bounds__(256) gemm_bf3(
    const bf16* __restrict__ Ah, const bf16* __restrict__ Al, int lda,
    const bf16* __restrict__ Bh, const bf16* __restrict__ Bl, int ldb,
    const float* __restrict__ bias,
    bf16* __restrict__ Ch, bf16* __restrict__ Cl, int ldc,
    int K, long sAz, long sBz, long sCz, float alpha)
{
    constexpr int NI = BN / 32;          // n8 frags per warp (warp N = BN/4)
    __shared__ bf16 sAh[2][128 * 24], sAl[2][128 * 24];
    __shared__ bf16 sBh[2][BN * 24],  sBl[2][BN * 24];

    const int tid = threadIdx.x;
    const int warp = tid >> 5, lane = tid & 31;
    const int g = lane >> 2, tig = lane & 3;
    const int wm = warp & 1, wn = warp >> 1;
    const int wm0 = wm * 64, wn0 = wn * (BN / 4);
    const int bm = blockIdx.y * 128, bn = blockIdx.x * BN;
    const long z = blockIdx.z;
    Ah += z * sAz; Al += z * sAz;
    Bh += z * sBz; Bl += z * sBz;
    Ch += z * sCz; Cl += z * sCz;

    float acc[4][NI][4];
#pragma unroll
    for (int mi = 0; mi < 4; mi++)
#pragma unroll
        for (int ni = 0; ni < NI; ni++)
#pragma unroll
            for (int q = 0; q < 4; q++) acc[mi][ni][q] = 0.f;

    auto load_tile = [&](int t, int buf) {
        const int k0 = t * 16;
        uint32_t dah = (uint32_t)__cvta_generic_to_shared(&sAh[buf][0]);
        uint32_t dal = (uint32_t)__cvta_generic_to_shared(&sAl[buf][0]);
        uint32_t dbh = (uint32_t)__cvta_generic_to_shared(&sBh[buf][0]);
        uint32_t dbl = (uint32_t)__cvta_generic_to_shared(&sBl[buf][0]);
        {
            int row = tid >> 1, half = tid & 1;
            uint32_t off = (uint32_t)(row * 24 + half * 8) * 2;
            long src = (long)(bm + row) * lda + k0 + half * 8;
            cp16(dah + off, Ah + src);
            cp16(dal + off, Al + src);
        }
        if (BN == 128 || tid < BN * 2) {
            int row = tid >> 1, half = tid & 1;
            uint32_t off = (uint32_t)(row * 24 + half * 8) * 2;
            long src = (long)(bn + row) * ldb + k0 + half * 8;
            cp16(dbh + off, Bh + src);
            cp16(dbl + off, Bl + src);
        }
    };

    load_tile(0, 0);
    CP_COMMIT();
    const int nt = K / 16;

    for (int t = 0; t < nt; t++) {
        if (t + 1 < nt) {
            load_tile(t + 1, (t + 1) & 1);
            CP_COMMIT();
            asm volatile("cp.async.wait_group 1;");
        } else {
            asm volatile("cp.async.wait_group 0;");
        }
        __syncthreads();
        const int buf = t & 1;
        const bf16* pah = sAh[buf];
        const bf16* pal = sAl[buf];
        const bf16* pbh = sBh[buf];
        const bf16* pbl = sBl[buf];

        uint32_t fah[4][4], fal[4][4];
#pragma unroll
        for (int mi = 0; mi < 4; mi++) {
            int b0 = (wm0 + mi * 16 + g) * 24 + tig * 2;
            fah[mi][0] = *(const uint32_t*)(pah + b0);
            fah[mi][1] = *(const uint32_t*)(pah + b0 + 192);
            fah[mi][2] = *(const uint32_t*)(pah + b0 + 8);
            fah[mi][3] = *(const uint32_t*)(pah + b0 + 200);
            fal[mi][0] = *(const uint32_t*)(pal + b0);
            fal[mi][1] = *(const uint32_t*)(pal + b0 + 192);
            fal[mi][2] = *(const uint32_t*)(pal + b0 + 8);
            fal[mi][3] = *(const uint32_t*)(pal + b0 + 200);
        }
#pragma unroll
        for (int ni = 0; ni < NI; ni++) {
            int c0 = (wn0 + ni * 8 + g) * 24 + tig * 2;
            uint32_t bh0 = *(const uint32_t*)(pbh + c0);
            uint32_t bh1 = *(const uint32_t*)(pbh + c0 + 8);
            uint32_t bl0 = *(const uint32_t*)(pbl + c0);
            uint32_t bl1 = *(const uint32_t*)(pbl + c0 + 8);
#pragma unroll
            for (int mi = 0; mi < 4; mi++) {
                MMA_BF16(acc[mi][ni], fah[mi], bh0, bh1);
                MMA_BF16(acc[mi][ni], fal[mi], bh0, bh1);
                MMA_BF16(acc[mi][ni], fah[mi], bl0, bl1);
            }
        }
        __syncthreads();
    }

    // epilogue: scale + bias + act, split to dual bf16 planes
#pragma unroll
    for (int mi = 0; mi < 4; mi++) {
#pragma unroll
        for (int ni = 0; ni < NI; ni++) {
            int col = bn + wn0 + ni * 8 + tig * 2;
            float b0 = 0.f, b1 = 0.f;
            if (bias) { b0 = bias[col]; b1 = bias[col + 1]; }
#pragma unroll
            for (int h2 = 0; h2 < 2; h2++) {
                int row = bm + wm0 + mi * 16 + g + h2 * 8;
                float v0 = acc[mi][ni][h2 * 2 + 0] * alpha + b0;
                float v1 = acc[mi][ni][h2 * 2 + 1] * alpha + b1;
                if (ACT == 1) { v0 = fmaxf(v0, 0.f); v1 = fmaxf(v1, 0.f); }
                if (ACT == 2) { v0 = tanhf(v0); v1 = tanhf(v1); }
                split2st(v0, v1, Ch, Cl, (long)row * ldc + col);
            }
        }
    }
}

// ---------------- conversions ---------------------------------------------
__global__ void conv_k(const float* __restrict__ in, bf16* __restrict__ oh,
                       bf16* __restrict__ ol, int n)
{
    int i = blockIdx.x * 256 + threadIdx.x;
    if (i < n) split1(in[i], oh, ol, i);
}

// W[K,N] fp32 -> out[N,K] dual-plane bf16
__global__ void convT_k(const float* __restrict__ in, bf16* __restrict__ oh,
                        bf16* __restrict__ ol, int K, int N)
{
    __shared__ float tile[32][33];
    const int k0 = blockIdx.y * 32, n0 = blockIdx.x * 32;
    const int tx = threadIdx.x, ty = threadIdx.y;
#pragma unroll
    for (int p = 0; p < 4; p++)
        tile[ty + p * 8][tx] = in[(long)(k0 + ty + p * 8) * N + n0 + tx];
    __syncthreads();
#pragma unroll
    for (int p = 0; p < 4; p++) {
        int n = n0 + ty + p * 8, k = k0 + tx;
        split1(tile[tx][ty + p * 8], oh, ol, (long)n * K + k);
    }
}

// V^T per head from qkv planes: vt[h][d][n] = qkv[n][512 + h*64 + d]
__global__ void vt_k(const bf16* __restrict__ qh, const bf16* __restrict__ ql,
                     bf16* __restrict__ vh, bf16* __restrict__ vl)
{
    __shared__ bf16 th[32][33], tl[32][33];
    const int h = blockIdx.z;
    const int n0 = blockIdx.x * 32, d0 = blockIdx.y * 32;
    const int tx = threadIdx.x, ty = threadIdx.y;
#pragma unroll
    for (int p = 0; p < 4; p++) {
        long src = (long)(n0 + ty + p * 8) * 768 + 512 + h * 64 + d0 + tx;
        th[ty + p * 8][tx] = qh[src];
        tl[ty + p * 8][tx] = ql[src];
    }
    __syncthreads();
#pragma unroll
    for (int p = 0; p < 4; p++) {
        long dst = (long)(h * 64 + d0 + ty + p * 8) * NN + n0 + tx;
        vh[dst] = th[tx][ty + p * 8];
        vl[dst] = tl[tx][ty + p * 8];
    }
}

// ---------------- row softmax (4096 cols), dual-plane in/out --------------
__global__ void __launch_bounds__(256) softmax_rows(bf16* __restrict__ H,
                                                    bf16* __restrict__ L)
{
    const long base = ((long)blockIdx.y * NN + blockIdx.x) * NN;
    const int t = threadIdx.x;
    const uint4* ph = (const uint4*)(H + base);
    const uint4* pl = (const uint4*)(L + base);
    uint4 uh[2] = { ph[2 * t], ph[2 * t + 1] };
    uint4 ul[2] = { pl[2 * t], pl[2 * t + 1] };
    float v[16];
#pragma unroll
    for (int q = 0; q < 2; q++) {
        uint32_t ah[4] = { uh[q].x, uh[q].y, uh[q].z, uh[q].w };
        uint32_t al[4] = { ul[q].x, ul[q].y, ul[q].z, ul[q].w };
#pragma unroll
        for (int j = 0; j < 4; j++) {
            float hx, hy, lx, ly;
            unp(ah[j], hx, hy); unp(al[j], lx, ly);
            v[q * 8 + j * 2]     = hx + lx;
            v[q * 8 + j * 2 + 1] = hy + ly;
        }
    }
    __shared__ float red[8];
    float m = -1e30f;
#pragma unroll
    for (int i = 0; i < 16; i++) m = fmaxf(m, v[i]);
#pragma unroll
    for (int k = 16; k; k >>= 1) m = fmaxf(m, __shfl_xor_sync(0xffffffffu, m, k));
    if ((t & 31) == 0) red[t >> 5] = m;
    __syncthreads();
    float M = -1e30f;
#pragma unroll
    for (int w = 0; w < 8; w++) M = fmaxf(M, red[w]);
    float s = 0.f;
#pragma unroll
    for (int i = 0; i < 16; i++) { v[i] = __expf(v[i] - M); s += v[i]; }
    __syncthreads();
#pragma unroll
    for (int k = 16; k; k >>= 1) s += __shfl_xor_sync(0xffffffffu, s, k);
    if ((t & 31) == 0) red[t >> 5] = s;
    __syncthreads();
    float tot = 0.f;
#pragma unroll
    for (int w = 0; w < 8; w++) tot += red[w];
    float inv = 1.f / tot;
#pragma unroll
    for (int q = 0; q < 2; q++) {
        uint32_t oh[4], ol2[4];
#pragma unroll
        for (int j = 0; j < 4; j++) {
            float v0 = v[q * 8 + j * 2] * inv, v1 = v[q * 8 + j * 2 + 1] * inv;
            bf16 h0 = __float2bfloat16(v0), h1 = __float2bfloat16(v1);
            float r0 = v0 - __bfloat162float(h0), r1 = v1 - __bfloat162float(h1);
            oh[j]  = pk(h0, h1);
            ol2[j] = pk(__float2bfloat16(r0), __float2bfloat16(r1));
        }
        ((uint4*)(H + base))[2 * t + q] = make_uint4(oh[0], oh[1], oh[2], oh[3]);
        ((uint4*)(L + base))[2 * t + q] = make_uint4(ol2[0], ol2[1], ol2[2], ol2[3]);
    }
}

// ---------------- top-16 per row (relu + diag mask, lowest-index ties) ----
__global__ void __launch_bounds__(256) topk_kernel(const bf16* __restrict__ Sh,
                                                   const bf16* __restrict__ Sl,
                                                   int* __restrict__ idx)
{
    const int row = blockIdx.x, t = threadIdx.x;
    float lv[16];
#pragma unroll
    for (int i = 0; i < 16; i++) {
        int j = i * 256 + t;
        float v = fmaxf(rec(Sh, Sl, (long)row * NN + j), 0.f);
        if (j == row) v = -1e9f;
        lv[i] = v;
    }
    __shared__ float sv[256];
    __shared__ int   si[256];
    for (int r = 0; r < 16; r++) {
        float bv = -2e9f; int bi = 0;
#pragma unroll
        for (int i = 0; i < 16; i++) {
            if (lv[i] > bv) { bv = lv[i]; bi = i * 256 + t; }
        }
        sv[t] = bv; si[t] = bi;
        __syncthreads();
        for (int s = 128; s > 0; s >>= 1) {
            if (t < s) {
                if (sv[t + s] > sv[t] || (sv[t + s] == sv[t] && si[t + s] < si[t])) {
                    sv[t] = sv[t + s]; si[t] = si[t + s];
                }
            }
            __syncthreads();
        }
        int winj = si[0];
        if (t == 0) idx[row * 16 + r] = winj;
        if ((winj & 255) == t) lv[winj >> 8] = -2e9f;
        __syncthreads();
    }
}

// ---------------- GAT score precompute ------------------------------------
__global__ void __launch_bounds__(256) gat_scores(const bf16* __restrict__ hh,
                                                  const bf16* __restrict__ hl,
                                                  const float* __restrict__ a_s,
                                                  const float* __restrict__ a_d,
                                                  float* __restrict__ ssrc,
                                                  float* __restrict__ sdst,
                                                  int heads)
{
    const int n = blockIdx.x, t = threadIdx.x;
    float hv = rec(hh, hl, (long)n * 256 + t);
    float ps = hv * a_s[t];
    float pd = hv * a_d[t];
#pragma unroll
    for (int m = 16; m; m >>= 1) {
        ps += __shfl_xor_sync(0xffffffffu, ps, m);
        pd += __shfl_xor_sync(0xffffffffu, pd, m);
    }
    __shared__ float ws[8], wd[8];
    if ((t & 31) == 0) { ws[t >> 5] = ps; wd[t >> 5] = pd; }
    __syncthreads();
    if (t < heads) {
        int wph = 8 / heads;
        float s = 0.f, d = 0.f;
        for (int w = 0; w < wph; w++) { s += ws[t * wph + w]; d += wd[t * wph + w]; }
        ssrc[n * heads + t] = s;
        sdst[n * heads + t] = d;
    }
}

// ---------------- GAT aggregation (17 in-edges per dst) -------------------
template<int HEADS>
__global__ void __launch_bounds__(256) gat_agg(const bf16* __restrict__ hh,
                                               const bf16* __restrict__ hl,
                                               const float* __restrict__ ssrc,
                                               const float* __restrict__ sdst,
                                               const int* __restrict__ idx,
                                               const float* __restrict__ bias,
                                               bf16* __restrict__ oh,
                                               bf16* __restrict__ ol,
                                               float* __restrict__ o32,
                                               int do_relu)
{
    const int i = blockIdx.x, t = threadIdx.x;
    __shared__ int   s_src[17];
    __shared__ float s_e[HEADS * 17];
    __shared__ float s_a[HEADS * 17];
    if (t < 16) s_src[t] = idx[i * 16 + t];
    if (t == 16) s_src[16] = i;
    __syncthreads();
    if (t < HEADS * 17) {
        int hh2 = t / 17, j = t % 17;
        float e = ssrc[s_src[j] * HEADS + hh2] + sdst[i * HEADS + hh2];
        s_e[t] = e > 0.f ? e : 0.2f * e;
    }
    __syncthreads();
    if (t < HEADS) {
        float m = -1e30f;
        for (int j = 0; j < 17; j++) m = fmaxf(m, s_e[t * 17 + j]);
        float s = 0.f;
        for (int j = 0; j < 17; j++) {
            float p = __expf(s_e[t * 17 + j] - m);
            s_a[t * 17 + j] = p; s += p;
        }
        float inv = 1.f / s;
        for (int j = 0; j < 17; j++) s_a[t * 17 + j] *= inv;
    }
    __syncthreads();
    const int hd = t / (256 / HEADS);
    float acc = 0.f;
#pragma unroll
    for (int j = 0; j < 17; j++)
        acc = fmaf(s_a[hd * 17 + j], rec(hh, hl, (long)s_src[j] * 256 + t), acc);
    float o = acc + bias[t];
    if (do_relu) o = fmaxf(o, 0.f);
    if (oh) split1(o, oh, ol, (long)i * 256 + t);
    else    o32[(long)i * 256 + t] = o;
}

// ---------------- residual + LayerNorm, dual-plane ------------------------
__global__ void __launch_bounds__(256) add_ln_kernel(const bf16* __restrict__ xh,
                                                     const bf16* __restrict__ xl,
                                                     const bf16* __restrict__ th,
                                                     const bf16* __restrict__ tl,
                                                     const float* __restrict__ g,
                                                     const float* __restrict__ b,
                                                     bf16* __restrict__ oh,
                                                     bf16* __restrict__ ol)
{
    const int n = blockIdx.x, t = threadIdx.x;
    const long off = (long)n * 256 + t;
    float v = rec(xh, xl, off) + rec(th, tl, off);
    __shared__ float red[8];
    float s = v;
#pragma unroll
    for (int m = 16; m; m >>= 1) s += __shfl_xor_sync(0xffffffffu, s, m);
    if ((t & 31) == 0) red[t >> 5] = s;
    __syncthreads();
    float tot = 0.f;
#pragma unroll
    for (int w = 0; w < 8; w++) tot += red[w];
    float mu = tot * (1.f / 256.f);
    float d = v - mu;
    float sq = d * d;
#pragma unroll
    for (int m = 16; m; m >>= 1) sq += __shfl_xor_sync(0xffffffffu, sq, m);
    __syncthreads();
    if ((t & 31) == 0) red[t >> 5] = sq;
    __syncthreads();
    float tv = 0.f;
#pragma unroll
    for (int w = 0; w < 8; w++) tv += red[w];
    float var = tv * (1.f / 256.f);
    split1(d * rsqrtf(var + 1e-5f) * g[t] + b[t], oh, ol, off);
}

// ---------------- dual-plane elementwise add ------------------------------
__global__ void add_pair(bf16* __restrict__ xh, bf16* __restrict__ xl,
                         const bf16* __restrict__ th, const bf16* __restrict__ tl)
{
    long i = (long)blockIdx.x * 256 + threadIdx.x;
    split1(rec(xh, xl, i) + rec(th, tl, i), xh, xl, i);
}

// ---------------- transpose [4096,256] fp32 -> [256,4096] -----------------
__global__ void transpose_kernel(const float* __restrict__ in, float* __restrict__ out)
{
    __shared__ float tile[32][33];
    const int bx = blockIdx.x * 32, by = blockIdx.y * 32;
    const int tx = threadIdx.x, ty = threadIdx.y;
#pragma unroll
    for (int p = 0; p < 4; p++)
        tile[ty + p * 8][tx] = in[(long)(by + ty + p * 8) * 256 + bx + tx];
    __syncthreads();
#pragma unroll
    for (int p = 0; p < 4; p++)
        out[(long)(bx + ty + p * 8) * 4096 + by + tx] = tile[tx][ty + p * 8];
}

// ---------------- launch ---------------------------------------------------
extern "C" void kernel_launch(void* const* d_in, const int* in_sizes, int n_in,
                              void* d_out, int out_size)
{
    const float* window   = (const float*)d_in[0];
    const float* gl_w     = (const float*)d_in[1];
    const float* gl_b     = (const float*)d_in[2];
    const float* enc_W    = (const float*)d_in[3];
    const float* enc_asrc = (const float*)d_in[4];
    const float* enc_adst = (const float*)d_in[5];
    const float* enc_b    = (const float*)d_in[6];
    const float* tr_wqkv  = (const float*)d_in[7];
    const float* tr_bqkv  = (const float*)d_in[8];
    const float* tr_wo    = (const float*)d_in[9];
    const float* tr_bo    = (const float*)d_in[10];
    const float* ln1g     = (const float*)d_in[11];
    const float* ln1b     = (const float*)d_in[12];
    const float* tr_w1    = (const float*)d_in[13];
    const float* tr_b1    = (const float*)d_in[14];
    const float* tr_w2    = (const float*)d_in[15];
    const float* tr_b2    = (const float*)d_in[16];
    const float* ln2g     = (const float*)d_in[17];
    const float* ln2b     = (const float*)d_in[18];
    const float* skip_w   = (const float*)d_in[19];
    const float* skip_b   = (const float*)d_in[20];
    const float* dec_W    = (const float*)d_in[21];
    const float* dec_asrc = (const float*)d_in[22];
    const float* dec_adst = (const float*)d_in[23];
    const float* dec_b    = (const float*)d_in[24];
    const float* dec_lW   = (const float*)d_in[25];
    const float* dec_lasrc= (const float*)d_in[26];
    const float* dec_ladst= (const float*)d_in[27];
    const float* dec_lb   = (const float*)d_in[28];

    bf16 *winh, *winl, *h0h, *h0l, *xh, *xl, *yh, *yl, *th, *tl;
    bf16 *qkvh, *qkvl, *ffh, *ffl, *vth, *vtl, *atth, *attl, *wh, *wl;
    float *tb, *ssrc, *sdst;
    int* idxb;
    cudaGetSymbolAddress((void**)&winh, g_win_h); cudaGetSymbolAddress((void**)&winl, g_win_l);
    cudaGetSymbolAddress((void**)&h0h,  g_h0_h);  cudaGetSymbolAddress((void**)&h0l,  g_h0_l);
    cudaGetSymbolAddress((void**)&xh,   g_x_h);   cudaGetSymbolAddress((void**)&xl,   g_x_l);
    cudaGetSymbolAddress((void**)&yh,   g_y_h);   cudaGetSymbolAddress((void**)&yl,   g_y_l);
    cudaGetSymbolAddress((void**)&th,   g_t_h);   cudaGetSymbolAddress((void**)&tl,   g_t_l);
    cudaGetSymbolAddress((void**)&qkvh, g_qkv_h); cudaGetSymbolAddress((void**)&qkvl, g_qkv_l);
    cudaGetSymbolAddress((void**)&ffh,  g_ff_h);  cudaGetSymbolAddress((void**)&ffl,  g_ff_l);
    cudaGetSymbolAddress((void**)&vth,  g_vt_h);  cudaGetSymbolAddress((void**)&vtl,  g_vt_l);
    cudaGetSymbolAddress((void**)&atth, g_att_h); cudaGetSymbolAddress((void**)&attl, g_att_l);
    cudaGetSymbolAddress((void**)&wh,   g_w_h);   cudaGetSymbolAddress((void**)&wl,   g_w_l);
    cudaGetSymbolAddress((void**)&tb,   g_tb);
    cudaGetSymbolAddress((void**)&ssrc, g_ssrc);  cudaGetSymbolAddress((void**)&sdst, g_sdst);
    cudaGetSymbolAddress((void**)&idxb, g_idx);

    // weight pool offsets (elements)
    const long O_GLW = 0,       O_ENCW = 65536,  O_WQKV = 262144, O_WO = 655360;
    const long O_W1 = 786432,   O_W2 = 1048576,  O_SKIP = 1310720;
    const long O_DECW = 1376256, O_DECL = 1507328;

    dim3 blk(256), tblk(32, 8);
    const long HS = (long)NN * NN;

    // ---- input + weight conversion to dual-plane bf16 ----
    conv_k<<<NN * DD / 256, blk>>>(window, winh, winl, NN * DD);
    convT_k<<<dim3(8, 8), tblk>>>(gl_w, wh + O_GLW, wl + O_GLW, 256, 256);
    for (int i = 0; i < 3; i++)
        convT_k<<<dim3(8, 8), tblk>>>(enc_W + (long)i * 65536, wh + O_ENCW + i * 65536,
                                      wl + O_ENCW + i * 65536, 256, 256);
    for (int i = 0; i < 2; i++) {
        conv_k<<<768, blk>>>(tr_wqkv + (long)i * 196608, wh + O_WQKV + i * 196608,
                             wl + O_WQKV + i * 196608, 196608);
        conv_k<<<256, blk>>>(tr_wo + (long)i * 65536, wh + O_WO + i * 65536,
                             wl + O_WO + i * 65536, 65536);
        convT_k<<<dim3(16, 8), tblk>>>(tr_w1 + (long)i * 131072, wh + O_W1 + i * 131072,
                                       wl + O_W1 + i * 131072, 256, 512);
        convT_k<<<dim3(8, 16), tblk>>>(tr_w2 + (long)i * 131072, wh + O_W2 + i * 131072,
                                       wl + O_W2 + i * 131072, 512, 256);
        convT_k<<<dim3(8, 8), tblk>>>(dec_W + (long)i * 65536, wh + O_DECW + i * 65536,
                                      wl + O_DECW + i * 65536, 256, 256);
    }
    convT_k<<<dim3(8, 8), tblk>>>(skip_w, wh + O_SKIP, wl + O_SKIP, 256, 256);
    convT_k<<<dim3(8, 8), tblk>>>(dec_lW, wh + O_DECL, wl + O_DECL, 256, 256);

    // ---- graph learning: h0 = tanh(win @ glW + b); sim = h0 @ h0^T; top-16
    gemm_bf3<64, 2><<<dim3(4, 32), blk>>>(winh, winl, DD, wh + O_GLW, wl + O_GLW, DD,
        gl_b, h0h, h0l, DD, DD, 0, 0, 0, 1.f);
    gemm_bf3<128, 0><<<dim3(32, 32), blk>>>(h0h, h0l, DD, h0h, h0l, DD,
        nullptr, atth, attl, NN, DD, 0, 0, 0, 1.f);
    topk_kernel<<<NN, blk>>>(atth, attl, idxb);

    // ---- encoder: 3x GAT(4 heads) + relu
    const bf16* xih = winh; const bf16* xil = winl;
    for (int i = 0; i < 3; i++) {
        gemm_bf3<64, 0><<<dim3(4, 32), blk>>>(xih, xil, DD,
            wh + O_ENCW + i * 65536, wl + O_ENCW + i * 65536, DD,
            nullptr, yh, yl, DD, DD, 0, 0, 0, 1.f);
        gat_scores<<<NN, blk>>>(yh, yl, enc_asrc + i * 256, enc_adst + i * 256, ssrc, sdst, 4);
        gat_agg<4><<<NN, blk>>>(yh, yl, ssrc, sdst, idxb, enc_b + i * DD, xh, xl, nullptr, 1);
        xih = xh; xil = xl;
    }

    // ---- transformer bottleneck: 2 layers
    for (int i = 0; i < 2; i++) {
        // qkv = x @ wqkv^T + bqkv   (K = DD = 256!)
        gemm_bf3<128, 0><<<dim3(6, 32), blk>>>(xh, xl, DD,
            wh + O_WQKV + i * 196608, wl + O_WQKV + i * 196608, DD,
            tr_bqkv + i * 768, qkvh, qkvl, 768, DD, 0, 0, 0, 1.f);
        // S_h = (Q_h @ K_h^T)/8, heads batched over z
        gemm_bf3<128, 0><<<dim3(32, 32, 4), blk>>>(qkvh, qkvl, 768,
            qkvh + 256, qkvl + 256, 768,
            nullptr, atth, attl, NN, 64, 64, 64, HS, 0.125f);
        softmax_rows<<<dim3(NN, 4), blk>>>(atth, attl);
        vt_k<<<dim3(NN / 32, 2, 4), tblk>>>(qkvh, qkvl, vth, vtl);
        // O_h = P_h @ V_h (B = V^T, k-major)
        gemm_bf3<64, 0><<<dim3(1, 32, 4), blk>>>(atth, attl, NN,
            vth, vtl, NN,
            nullptr, yh, yl, DD, NN, HS, 64L * NN, 64, 1.f);
        gemm_bf3<64, 0><<<dim3(4, 32), blk>>>(yh, yl, DD,
            wh + O_WO + i * 65536, wl + O_WO + i * 65536, DD,
            tr_bo + i * DD, th, tl, DD, DD, 0, 0, 0, 1.f);
        add_ln_kernel<<<NN, blk>>>(xh, xl, th, tl, ln1g + i * DD, ln1b + i * DD, xh, xl);
        gemm_bf3<128, 1><<<dim3(4, 32), blk>>>(xh, xl, DD,
            wh + O_W1 + i * 131072, wl + O_W1 + i * 131072, DD,
            tr_b1 + i * 512, ffh, ffl, 512, DD, 0, 0, 0, 1.f);
        gemm_bf3<64, 0><<<dim3(4, 32), blk>>>(ffh, ffl, 512,
            wh + O_W2 + i * 131072, wl + O_W2 + i * 131072, 512,
            tr_b2 + i * DD, th, tl, DD, 512, 0, 0, 0, 1.f);
        add_ln_kernel<<<NN, blk>>>(xh, xl, th, tl, ln2g + i * DD, ln2b + i * DD, xh, xl);
    }

    // ---- skip connection
    gemm_bf3<64, 0><<<dim3(4, 32), blk>>>(winh, winl, DD, wh + O_SKIP, wl + O_SKIP, DD,
        skip_b, th, tl, DD, DD, 0, 0, 0, 1.f);
    add_pair<<<NN, blk>>>(xh, xl, th, tl);

    // ---- decoder: 2x GAT(4 heads)+relu, then single-head GAT
    for (int i = 0; i < 2; i++) {
        gemm_bf3<64, 0><<<dim3(4, 32), blk>>>(xh, xl, DD,
            wh + O_DECW + i * 65536, wl + O_DECW + i * 65536, DD,
            nullptr, yh, yl, DD, DD, 0, 0, 0, 1.f);
        gat_scores<<<NN, blk>>>(yh, yl, dec_asrc + i * 256, dec_adst + i * 256, ssrc, sdst, 4);
        gat_agg<4><<<NN, blk>>>(yh, yl, ssrc, sdst, idxb, dec_b + i * DD, xh, xl, nullptr, 1);
    }
    gemm_bf3<64, 0><<<dim3(4, 32), blk>>>(xh, xl, DD, wh + O_DECL, wl + O_DECL, DD,
        nullptr, yh, yl, DD, DD, 0, 0, 0, 1.f);
    gat_scores<<<NN, blk>>>(yh, yl, dec_lasrc, dec_ladst, ssrc, sdst, 1);
    gat_agg<1><<<NN, blk>>>(yh, yl, ssrc, sdst, idxb, dec_lb, nullptr, nullptr, tb, 0);

    // ---- output: transpose to [256, 4096]
    transpose_kernel<<<dim3(8, 128), dim3(32, 8)>>>(tb, (float*)d_out);
}

// round 7
// speedup vs baseline: 1.5086x; 1.0318x over previous
#include <cuda_runtime.h>
#include <cuda_bf16.h>
#include <math.h>
#include <stdint.h>

typedef __nv_bfloat16 bf16;

#define NN 4096
#define DD 256

// ---------------- scratch (device globals; no allocation) ----------------
__device__ bf16 g_win_h[NN * DD], g_win_l[NN * DD];
__device__ bf16 g_h0_h[NN * DD],  g_h0_l[NN * DD];
__device__ bf16 g_x_h[NN * DD],   g_x_l[NN * DD];
__device__ bf16 g_y_h[NN * DD],   g_y_l[NN * DD];
__device__ bf16 g_t_h[NN * DD],   g_t_l[NN * DD];
__device__ bf16 g_qkv_h[NN * 768], g_qkv_l[NN * 768];
__device__ bf16 g_ff_h[NN * 512],  g_ff_l[NN * 512];
__device__ bf16 g_vt_h[4 * 64 * NN], g_vt_l[4 * 64 * NN];
__device__ bf16 g_att_h[4L * NN * NN], g_att_l[4L * NN * NN];  // 128MB each
#define WPOOL 1572864
__device__ bf16 g_w_h[WPOOL], g_w_l[WPOOL];
__device__ float g_tb[NN * DD];
__device__ float g_ssrc[NN * 4], g_sdst[NN * 4];
__device__ int   g_idx[NN * 16];

// ---------------- helpers -------------------------------------------------
__device__ __forceinline__ void cp16(uint32_t dst, const void* src) {
    asm volatile("cp.async.cg.shared.global [%0], [%1], 16;" :: "r"(dst), "l"(src));
}
#define CP_COMMIT() asm volatile("cp.async.commit_group;")

__device__ __forceinline__ float rec(const bf16* H, const bf16* L, long i) {
    return __bfloat162float(H[i]) + __bfloat162float(L[i]);
}
__device__ __forceinline__ void split1(float v, bf16* H, bf16* L, long off) {
    bf16 h = __float2bfloat16(v);
    H[off] = h;
    L[off] = __float2bfloat16(v - __bfloat162float(h));
}
__device__ __forceinline__ uint32_t pk(bf16 a, bf16 b) {
    __nv_bfloat162 t = __halves2bfloat162(a, b);
    return *(uint32_t*)&t;
}
__device__ __forceinline__ void split2st(float v0, float v1, bf16* H, bf16* L, long off) {
    bf16 h0 = __float2bfloat16(v0), h1 = __float2bfloat16(v1);
    float r0 = v0 - __bfloat162float(h0), r1 = v1 - __bfloat162float(h1);
    *(uint32_t*)(H + off) = pk(h0, h1);
    *(uint32_t*)(L + off) = pk(__float2bfloat16(r0), __float2bfloat16(r1));
}
__device__ __forceinline__ void unp(uint32_t u, float& a, float& b) {
    __nv_bfloat162 t = *(__nv_bfloat162*)&u;
    a = __bfloat162float(t.x); b = __bfloat162float(t.y);
}

#define MMA_BF16(c, a, b0, b1) \
    asm volatile("mma.sync.aligned.m16n8k16.row.col.f32.bf16.bf16.f32 " \
                 "{%0,%1,%2,%3},{%4,%5,%6,%7},{%8,%9},{%0,%1,%2,%3};" \
                 : "+f"((c)[0]), "+f"((c)[1]), "+f"((c)[2]), "+f"((c)[3]) \
                 : "r"((a)[0]), "r"((a)[1]), "r"((a)[2]), "r"((a)[3]), \
                   "r"(b0), "r"(b1))

#define LDSM4(r, addr) \
    asm volatile("ldmatrix.sync.aligned.m8n8.x4.shared.b16 {%0,%1,%2,%3}, [%4];" \
                 : "=r"((r)[0]), "=r"((r)[1]), "=r"((r)[2]), "=r"((r)[3]) \
                 : "r"(addr))

// ---------------- split-bf16 3-product GEMM (both operands k-major) -------
// C[M,N] = act(alpha * A @ B^T (+bias)); A[M,K], B[N,K]; all dual-plane bf16.
// BM=128 fixed; z batch via element strides. ACT: 0 none, 1 relu, 2 tanh.
template<int BN, int ACT>
__global__ void __launch_bounds__(256) gemm_bf3(
    const bf16* __restrict__ Ah, const bf16* __restrict__ Al, int lda,
    const bf16* __restrict__ Bh, const bf16* __restrict__ Bl, int ldb,
    const float* __restrict__ bias,
    bf16* __restrict__ Ch, bf16* __restrict__ Cl, int ldc,
    int K, long sAz, long sBz, long sCz, float alpha)
{
    constexpr int NI = BN / 32;          // n8 frags per warp (warp N = BN/4)
    __shared__ bf16 sAh[2][128 * 24], sAl[2][128 * 24];
    __shared__ bf16 sBh[2][BN * 24],  sBl[2][BN * 24];

    const int tid = threadIdx.x;
    const int warp = tid >> 5, lane = tid & 31;
    const int g = lane >> 2, tig = lane & 3;
    const int wm = warp & 1, wn = warp >> 1;
    const int wm0 = wm * 64, wn0 = wn * (BN / 4);
    const int bm = blockIdx.y * 128, bn = blockIdx.x * BN;
    const long z = blockIdx.z;
    Ah += z * sAz; Al += z * sAz;
    Bh += z * sBz; Bl += z * sBz;
    Ch += z * sCz; Cl += z * sCz;

    // ldmatrix per-thread byte offsets (within a plane buffer)
    // A x4: lanes 0-15 rows m0-15 (k=0), lanes 16-31 rows m0-15 (k=8)
    const uint32_t offA = (uint32_t)(((wm0 + (lane & 15)) * 24 + (lane >> 4) * 8) * 2);
    // B x4: covers two n8 tiles: lane>>4 selects tile, lane>>3&1 selects k half
    const uint32_t offB = (uint32_t)(((wn0 + ((lane >> 4) & 1) * 8 + (lane & 7)) * 24
                                      + ((lane >> 3) & 1) * 8) * 2);
    uint32_t bAh[2] = { (uint32_t)__cvta_generic_to_shared(&sAh[0][0]),
                        (uint32_t)__cvta_generic_to_shared(&sAh[1][0]) };
    uint32_t bAl[2] = { (uint32_t)__cvta_generic_to_shared(&sAl[0][0]),
                        (uint32_t)__cvta_generic_to_shared(&sAl[1][0]) };
    uint32_t bBh[2] = { (uint32_t)__cvta_generic_to_shared(&sBh[0][0]),
                        (uint32_t)__cvta_generic_to_shared(&sBh[1][0]) };
    uint32_t bBl[2] = { (uint32_t)__cvta_generic_to_shared(&sBl[0][0]),
                        (uint32_t)__cvta_generic_to_shared(&sBl[1][0]) };

    float acc[4][NI][4];
#pragma unroll
    for (int mi = 0; mi < 4; mi++)
#pragma unroll
        for (int ni = 0; ni < NI; ni++)
#pragma unroll
            for (int q = 0; q < 4; q++) acc[mi][ni][q] = 0.f;

    auto load_tile = [&](int t, int buf) {
        const int k0 = t * 16;
        {
            int row = tid >> 1, half = tid & 1;
            uint32_t off = (uint32_t)(row * 24 + half * 8) * 2;
            long src = (long)(bm + row) * lda + k0 + half * 8;
            cp16(bAh[buf] + off, Ah + src);
            cp16(bAl[buf] + off, Al + src);
        }
        if (BN == 128 || tid < BN * 2) {
            int row = tid >> 1, half = tid & 1;
            uint32_t off = (uint32_t)(row * 24 + half * 8) * 2;
            long src = (long)(bn + row) * ldb + k0 + half * 8;
            cp16(bBh[buf] + off, Bh + src);
            cp16(bBl[buf] + off, Bl + src);
        }
    };

    load_tile(0, 0);
    CP_COMMIT();
    const int nt = K / 16;

    for (int t = 0; t < nt; t++) {
        if (t + 1 < nt) {
            load_tile(t + 1, (t + 1) & 1);
            CP_COMMIT();
            asm volatile("cp.async.wait_group 1;");
        } else {
            asm volatile("cp.async.wait_group 0;");
        }
        __syncthreads();
        const int buf = t & 1;

        uint32_t fah[4][4], fal[4][4];
#pragma unroll
        for (int mi = 0; mi < 4; mi++) {
            LDSM4(fah[mi], bAh[buf] + offA + mi * 768);   // 16 rows * 48B
            LDSM4(fal[mi], bAl[buf] + offA + mi * 768);
        }
        uint32_t bh[NI][2], bl[NI][2];
#pragma unroll
        for (int pi = 0; pi < NI / 2; pi++) {
            LDSM4(bh[2 * pi], bBh[buf] + offB + pi * 768);
            LDSM4(bl[2 * pi], bBl[buf] + offB + pi * 768);
        }
#pragma unroll
        for (int ni = 0; ni < NI; ni++) {
#pragma unroll
            for (int mi = 0; mi < 4; mi++) {
                MMA_BF16(acc[mi][ni], fah[mi], bh[ni][0], bh[ni][1]);
                MMA_BF16(acc[mi][ni], fal[mi], bh[ni][0], bh[ni][1]);
                MMA_BF16(acc[mi][ni], fah[mi], bl[ni][0], bl[ni][1]);
            }
        }
        __syncthreads();
    }

    // epilogue: scale + bias + act, split to dual bf16 planes
#pragma unroll
    for (int mi = 0; mi < 4; mi++) {
#pragma unroll
        for (int ni = 0; ni < NI; ni++) {
            int col = bn + wn0 + ni * 8 + tig * 2;
            float b0 = 0.f, b1 = 0.f;
            if (bias) { b0 = bias[col]; b1 = bias[col + 1]; }
#pragma unroll
            for (int h2 = 0; h2 < 2; h2++) {
                int row = bm + wm0 + mi * 16 + g + h2 * 8;
                float v0 = acc[mi][ni][h2 * 2 + 0] * alpha + b0;
                float v1 = acc[mi][ni][h2 * 2 + 1] * alpha + b1;
                if (ACT == 1) { v0 = fmaxf(v0, 0.f); v1 = fmaxf(v1, 0.f); }
                if (ACT == 2) { v0 = tanhf(v0); v1 = tanhf(v1); }
                split2st(v0, v1, Ch, Cl, (long)row * ldc + col);
            }
        }
    }
}

// ---------------- conversions ---------------------------------------------
__global__ void conv_k(const float* __restrict__ in, bf16* __restrict__ oh,
                       bf16* __restrict__ ol, int n)
{
    int i = blockIdx.x * 256 + threadIdx.x;
    if (i < n) split1(in[i], oh, ol, i);
}

// W[K,N] fp32 -> out[N,K] dual-plane bf16
__global__ void convT_k(const float* __restrict__ in, bf16* __restrict__ oh,
                        bf16* __restrict__ ol, int K, int N)
{
    __shared__ float tile[32][33];
    const int k0 = blockIdx.y * 32, n0 = blockIdx.x * 32;
    const int tx = threadIdx.x, ty = threadIdx.y;
#pragma unroll
    for (int p = 0; p < 4; p++)
        tile[ty + p * 8][tx] = in[(long)(k0 + ty + p * 8) * N + n0 + tx];
    __syncthreads();
#pragma unroll
    for (int p = 0; p < 4; p++) {
        int n = n0 + ty + p * 8, k = k0 + tx;
        split1(tile[tx][ty + p * 8], oh, ol, (long)n * K + k);
    }
}

// V^T per head from qkv planes: vt[h][d][n] = qkv[n][512 + h*64 + d]
__global__ void vt_k(const bf16* __restrict__ qh, const bf16* __restrict__ ql,
                     bf16* __restrict__ vh, bf16* __restrict__ vl)
{
    __shared__ bf16 th[32][33], tl[32][33];
    const int h = blockIdx.z;
    const int n0 = blockIdx.x * 32, d0 = blockIdx.y * 32;
    const int tx = threadIdx.x, ty = threadIdx.y;
#pragma unroll
    for (int p = 0; p < 4; p++) {
        long src = (long)(n0 + ty + p * 8) * 768 + 512 + h * 64 + d0 + tx;
        th[ty + p * 8][tx] = qh[src];
        tl[ty + p * 8][tx] = ql[src];
    }
    __syncthreads();
#pragma unroll
    for (int p = 0; p < 4; p++) {
        long dst = (long)(h * 64 + d0 + ty + p * 8) * NN + n0 + tx;
        vh[dst] = th[tx][ty + p * 8];
        vl[dst] = tl[tx][ty + p * 8];
    }
}

// ---------------- row softmax (4096 cols), dual-plane in/out --------------
__global__ void __launch_bounds__(256) softmax_rows(bf16* __restrict__ H,
                                                    bf16* __restrict__ L)
{
    const long base = ((long)blockIdx.y * NN + blockIdx.x) * NN;
    const int t = threadIdx.x;
    const uint4* ph = (const uint4*)(H + base);
    const uint4* pl = (const uint4*)(L + base);
    uint4 uh[2] = { ph[2 * t], ph[2 * t + 1] };
    uint4 ul[2] = { pl[2 * t], pl[2 * t + 1] };
    float v[16];
#pragma unroll
    for (int q = 0; q < 2; q++) {
        uint32_t ah[4] = { uh[q].x, uh[q].y, uh[q].z, uh[q].w };
        uint32_t al[4] = { ul[q].x, ul[q].y, ul[q].z, ul[q].w };
#pragma unroll
        for (int j = 0; j < 4; j++) {
            float hx, hy, lx, ly;
            unp(ah[j], hx, hy); unp(al[j], lx, ly);
            v[q * 8 + j * 2]     = hx + lx;
            v[q * 8 + j * 2 + 1] = hy + ly;
        }
    }
    __shared__ float red[8];
    float m = -1e30f;
#pragma unroll
    for (int i = 0; i < 16; i++) m = fmaxf(m, v[i]);
#pragma unroll
    for (int k = 16; k; k >>= 1) m = fmaxf(m, __shfl_xor_sync(0xffffffffu, m, k));
    if ((t & 31) == 0) red[t >> 5] = m;
    __syncthreads();
    float M = -1e30f;
#pragma unroll
    for (int w = 0; w < 8; w++) M = fmaxf(M, red[w]);
    float s = 0.f;
#pragma unroll
    for (int i = 0; i < 16; i++) { v[i] = __expf(v[i] - M); s += v[i]; }
    __syncthreads();
#pragma unroll
    for (int k = 16; k; k >>= 1) s += __shfl_xor_sync(0xffffffffu, s, k);
    if ((t & 31) == 0) red[t >> 5] = s;
    __syncthreads();
    float tot = 0.f;
#pragma unroll
    for (int w = 0; w < 8; w++) tot += red[w];
    float inv = 1.f / tot;
#pragma unroll
    for (int q = 0; q < 2; q++) {
        uint32_t oh[4], ol2[4];
#pragma unroll
        for (int j = 0; j < 4; j++) {
            float v0 = v[q * 8 + j * 2] * inv, v1 = v[q * 8 + j * 2 + 1] * inv;
            bf16 h0 = __float2bfloat16(v0), h1 = __float2bfloat16(v1);
            float r0 = v0 - __bfloat162float(h0), r1 = v1 - __bfloat162float(h1);
            oh[j]  = pk(h0, h1);
            ol2[j] = pk(__float2bfloat16(r0), __float2bfloat16(r1));
        }
        ((uint4*)(H + base))[2 * t + q] = make_uint4(oh[0], oh[1], oh[2], oh[3]);
        ((uint4*)(L + base))[2 * t + q] = make_uint4(ol2[0], ol2[1], ol2[2], ol2[3]);
    }
}

// ---------------- top-16 per row (relu + diag mask, lowest-index ties) ----
__global__ void __launch_bounds__(256) topk_kernel(const bf16* __restrict__ Sh,
                                                   const bf16* __restrict__ Sl,
                                                   int* __restrict__ idx)
{
    const int row = blockIdx.x, t = threadIdx.x;
    float lv[16];
#pragma unroll
    for (int i = 0; i < 16; i++) {
        int j = i * 256 + t;
        float v = fmaxf(rec(Sh, Sl, (long)row * NN + j), 0.f);
        if (j == row) v = -1e9f;
        lv[i] = v;
    }
    __shared__ float sv[256];
    __shared__ int   si[256];
    for (int r = 0; r < 16; r++) {
        float bv = -2e9f; int bi = 0;
#pragma unroll
        for (int i = 0; i < 16; i++) {
            if (lv[i] > bv) { bv = lv[i]; bi = i * 256 + t; }
        }
        sv[t] = bv; si[t] = bi;
        __syncthreads();
        for (int s = 128; s > 0; s >>= 1) {
            if (t < s) {
                if (sv[t + s] > sv[t] || (sv[t + s] == sv[t] && si[t + s] < si[t])) {
                    sv[t] = sv[t + s]; si[t] = si[t + s];
                }
            }
            __syncthreads();
        }
        int winj = si[0];
        if (t == 0) idx[row * 16 + r] = winj;
        if ((winj & 255) == t) lv[winj >> 8] = -2e9f;
        __syncthreads();
    }
}

// ---------------- GAT score precompute ------------------------------------
__global__ void __launch_bounds__(256) gat_scores(const bf16* __restrict__ hh,
                                                  const bf16* __restrict__ hl,
                                                  const float* __restrict__ a_s,
                                                  const float* __restrict__ a_d,
                                                  float* __restrict__ ssrc,
                                                  float* __restrict__ sdst,
                                                  int heads)
{
    const int n = blockIdx.x, t = threadIdx.x;
    float hv = rec(hh, hl, (long)n * 256 + t);
    float ps = hv * a_s[t];
    float pd = hv * a_d[t];
#pragma unroll
    for (int m = 16; m; m >>= 1) {
        ps += __shfl_xor_sync(0xffffffffu, ps, m);
        pd += __shfl_xor_sync(0xffffffffu, pd, m);
    }
    __shared__ float ws[8], wd[8];
    if ((t & 31) == 0) { ws[t >> 5] = ps; wd[t >> 5] = pd; }
    __syncthreads();
    if (t < heads) {
        int wph = 8 / heads;
        float s = 0.f, d = 0.f;
        for (int w = 0; w < wph; w++) { s += ws[t * wph + w]; d += wd[t * wph + w]; }
        ssrc[n * heads + t] = s;
        sdst[n * heads + t] = d;
    }
}

// ---------------- GAT aggregation (17 in-edges per dst) -------------------
template<int HEADS>
__global__ void __launch_bounds__(256) gat_agg(const bf16* __restrict__ hh,
                                               const bf16* __restrict__ hl,
                                               const float* __restrict__ ssrc,
                                               const float* __restrict__ sdst,
                                               const int* __restrict__ idx,
                                               const float* __restrict__ bias,
                                               bf16* __restrict__ oh,
                                               bf16* __restrict__ ol,
                                               float* __restrict__ o32,
                                               int do_relu)
{
    const int i = blockIdx.x, t = threadIdx.x;
    __shared__ int   s_src[17];
    __shared__ float s_e[HEADS * 17];
    __shared__ float s_a[HEADS * 17];
    if (t < 16) s_src[t] = idx[i * 16 + t];
    if (t == 16) s_src[16] = i;
    __syncthreads();
    if (t < HEADS * 17) {
        int hh2 = t / 17, j = t % 17;
        float e = ssrc[s_src[j] * HEADS + hh2] + sdst[i * HEADS + hh2];
        s_e[t] = e > 0.f ? e : 0.2f * e;
    }
    __syncthreads();
    if (t < HEADS) {
        float m = -1e30f;
        for (int j = 0; j < 17; j++) m = fmaxf(m, s_e[t * 17 + j]);
        float s = 0.f;
        for (int j = 0; j < 17; j++) {
            float p = __expf(s_e[t * 17 + j] - m);
            s_a[t * 17 + j] = p; s += p;
        }
        float inv = 1.f / s;
        for (int j = 0; j < 17; j++) s_a[t * 17 + j] *= inv;
    }
    __syncthreads();
    const int hd = t / (256 / HEADS);
    float acc = 0.f;
#pragma unroll
    for (int j = 0; j < 17; j++)
        acc = fmaf(s_a[hd * 17 + j], rec(hh, hl, (long)s_src[j] * 256 + t), acc);
    float o = acc + bias[t];
    if (do_relu) o = fmaxf(o, 0.f);
    if (oh) split1(o, oh, ol, (long)i * 256 + t);
    else    o32[(long)i * 256 + t] = o;
}

// ---------------- residual + LayerNorm, dual-plane ------------------------
__global__ void __launch_bounds__(256) add_ln_kernel(const bf16* __restrict__ xh,
                                                     const bf16* __restrict__ xl,
                                                     const bf16* __restrict__ th,
                                                     const bf16* __restrict__ tl,
                                                     const float* __restrict__ g,
                                                     const float* __restrict__ b,
                                                     bf16* __restrict__ oh,
                                                     bf16* __restrict__ ol)
{
    const int n = blockIdx.x, t = threadIdx.x;
    const long off = (long)n * 256 + t;
    float v = rec(xh, xl, off) + rec(th, tl, off);
    __shared__ float red[8];
    float s = v;
#pragma unroll
    for (int m = 16; m; m >>= 1) s += __shfl_xor_sync(0xffffffffu, s, m);
    if ((t & 31) == 0) red[t >> 5] = s;
    __syncthreads();
    float tot = 0.f;
#pragma unroll
    for (int w = 0; w < 8; w++) tot += red[w];
    float mu = tot * (1.f / 256.f);
    float d = v - mu;
    float sq = d * d;
#pragma unroll
    for (int m = 16; m; m >>= 1) sq += __shfl_xor_sync(0xffffffffu, sq, m);
    __syncthreads();
    if ((t & 31) == 0) red[t >> 5] = sq;
    __syncthreads();
    float tv = 0.f;
#pragma unroll
    for (int w = 0; w < 8; w++) tv += red[w];
    float var = tv * (1.f / 256.f);
    split1(d * rsqrtf(var + 1e-5f) * g[t] + b[t], oh, ol, off);
}

// ---------------- dual-plane elementwise add ------------------------------
__global__ void add_pair(bf16* __restrict__ xh, bf16* __restrict__ xl,
                         const bf16* __restrict__ th, const bf16* __restrict__ tl)
{
    long i = (long)blockIdx.x * 256 + threadIdx.x;
    split1(rec(xh, xl, i) + rec(th, tl, i), xh, xl, i);
}

// ---------------- transpose [4096,256] fp32 -> [256,4096] -----------------
__global__ void transpose_kernel(const float* __restrict__ in, float* __restrict__ out)
{
    __shared__ float tile[32][33];
    const int bx = blockIdx.x * 32, by = blockIdx.y * 32;
    const int tx = threadIdx.x, ty = threadIdx.y;
#pragma unroll
    for (int p = 0; p < 4; p++)
        tile[ty + p * 8][tx] = in[(long)(by + ty + p * 8) * 256 + bx + tx];
    __syncthreads();
#pragma unroll
    for (int p = 0; p < 4; p++)
        out[(long)(bx + ty + p * 8) * 4096 + by + tx] = tile[tx][ty + p * 8];
}

// ---------------- launch ---------------------------------------------------
extern "C" void kernel_launch(void* const* d_in, const int* in_sizes, int n_in,
                              void* d_out, int out_size)
{
    const float* window   = (const float*)d_in[0];
    const float* gl_w     = (const float*)d_in[1];
    const float* gl_b     = (const float*)d_in[2];
    const float* enc_W    = (const float*)d_in[3];
    const float* enc_asrc = (const float*)d_in[4];
    const float* enc_adst = (const float*)d_in[5];
    const float* enc_b    = (const float*)d_in[6];
    const float* tr_wqkv  = (const float*)d_in[7];
    const float* tr_bqkv  = (const float*)d_in[8];
    const float* tr_wo    = (const float*)d_in[9];
    const float* tr_bo    = (const float*)d_in[10];
    const float* ln1g     = (const float*)d_in[11];
    const float* ln1b     = (const float*)d_in[12];
    const float* tr_w1    = (const float*)d_in[13];
    const float* tr_b1    = (const float*)d_in[14];
    const float* tr_w2    = (const float*)d_in[15];
    const float* tr_b2    = (const float*)d_in[16];
    const float* ln2g     = (const float*)d_in[17];
    const float* ln2b     = (const float*)d_in[18];
    const float* skip_w   = (const float*)d_in[19];
    const float* skip_b   = (const float*)d_in[20];
    const float* dec_W    = (const float*)d_in[21];
    const float* dec_asrc = (const float*)d_in[22];
    const float* dec_adst = (const float*)d_in[23];
    const float* dec_b    = (const float*)d_in[24];
    const float* dec_lW   = (const float*)d_in[25];
    const float* dec_lasrc= (const float*)d_in[26];
    const float* dec_ladst= (const float*)d_in[27];
    const float* dec_lb   = (const float*)d_in[28];

    bf16 *winh, *winl, *h0h, *h0l, *xh, *xl, *yh, *yl, *th, *tl;
    bf16 *qkvh, *qkvl, *ffh, *ffl, *vth, *vtl, *atth, *attl, *wh, *wl;
    float *tb, *ssrc, *sdst;
    int* idxb;
    cudaGetSymbolAddress((void**)&winh, g_win_h); cudaGetSymbolAddress((void**)&winl, g_win_l);
    cudaGetSymbolAddress((void**)&h0h,  g_h0_h);  cudaGetSymbolAddress((void**)&h0l,  g_h0_l);
    cudaGetSymbolAddress((void**)&xh,   g_x_h);   cudaGetSymbolAddress((void**)&xl,   g_x_l);
    cudaGetSymbolAddress((void**)&yh,   g_y_h);   cudaGetSymbolAddress((void**)&yl,   g_y_l);
    cudaGetSymbolAddress((void**)&th,   g_t_h);   cudaGetSymbolAddress((void**)&tl,   g_t_l);
    cudaGetSymbolAddress((void**)&qkvh, g_qkv_h); cudaGetSymbolAddress((void**)&qkvl, g_qkv_l);
    cudaGetSymbolAddress((void**)&ffh,  g_ff_h);  cudaGetSymbolAddress((void**)&ffl,  g_ff_l);
    cudaGetSymbolAddress((void**)&vth,  g_vt_h);  cudaGetSymbolAddress((void**)&vtl,  g_vt_l);
    cudaGetSymbolAddress((void**)&atth, g_att_h); cudaGetSymbolAddress((void**)&attl, g_att_l);
    cudaGetSymbolAddress((void**)&wh,   g_w_h);   cudaGetSymbolAddress((void**)&wl,   g_w_l);
    cudaGetSymbolAddress((void**)&tb,   g_tb);
    cudaGetSymbolAddress((void**)&ssrc, g_ssrc);  cudaGetSymbolAddress((void**)&sdst, g_sdst);
    cudaGetSymbolAddress((void**)&idxb, g_idx);

    // weight pool offsets (elements)
    const long O_GLW = 0,       O_ENCW = 65536,  O_WQKV = 262144, O_WO = 655360;
    const long O_W1 = 786432,   O_W2 = 1048576,  O_SKIP = 1310720;
    const long O_DECW = 1376256, O_DECL = 1507328;

    dim3 blk(256), tblk(32, 8);
    const long HS = (long)NN * NN;

    // ---- input + weight conversion to dual-plane bf16 ----
    conv_k<<<NN * DD / 256, blk>>>(window, winh, winl, NN * DD);
    convT_k<<<dim3(8, 8), tblk>>>(gl_w, wh + O_GLW, wl + O_GLW, 256, 256);
    for (int i = 0; i < 3; i++)
        convT_k<<<dim3(8, 8), tblk>>>(enc_W + (long)i * 65536, wh + O_ENCW + i * 65536,
                                      wl + O_ENCW + i * 65536, 256, 256);
    for (int i = 0; i < 2; i++) {
        conv_k<<<768, blk>>>(tr_wqkv + (long)i * 196608, wh + O_WQKV + i * 196608,
                             wl + O_WQKV + i * 196608, 196608);
        conv_k<<<256, blk>>>(tr_wo + (long)i * 65536, wh + O_WO + i * 65536,
                             wl + O_WO + i * 65536, 65536);
        convT_k<<<dim3(16, 8), tblk>>>(tr_w1 + (long)i * 131072, wh + O_W1 + i * 131072,
                                       wl + O_W1 + i * 131072, 256, 512);
        convT_k<<<dim3(8, 16), tblk>>>(tr_w2 + (long)i * 131072, wh + O_W2 + i * 131072,
                                       wl + O_W2 + i * 131072, 512, 256);
        convT_k<<<dim3(8, 8), tblk>>>(dec_W + (long)i * 65536, wh + O_DECW + i * 65536,
                                      wl + O_DECW + i * 65536, 256, 256);
    }
    convT_k<<<dim3(8, 8), tblk>>>(skip_w, wh + O_SKIP, wl + O_SKIP, 256, 256);
    convT_k<<<dim3(8, 8), tblk>>>(dec_lW, wh + O_DECL, wl + O_DECL, 256, 256);

    // ---- graph learning: h0 = tanh(win @ glW + b); sim = h0 @ h0^T; top-16
    gemm_bf3<64, 2><<<dim3(4, 32), blk>>>(winh, winl, DD, wh + O_GLW, wl + O_GLW, DD,
        gl_b, h0h, h0l, DD, DD, 0, 0, 0, 1.f);
    gemm_bf3<128, 0><<<dim3(32, 32), blk>>>(h0h, h0l, DD, h0h, h0l, DD,
        nullptr, atth, attl, NN, DD, 0, 0, 0, 1.f);
    topk_kernel<<<NN, blk>>>(atth, attl, idxb);

    // ---- encoder: 3x GAT(4 heads) + relu
    const bf16* xih = winh; const bf16* xil = winl;
    for (int i = 0; i < 3; i++) {
        gemm_bf3<64, 0><<<dim3(4, 32), blk>>>(xih, xil, DD,
            wh + O_ENCW + i * 65536, wl + O_ENCW + i * 65536, DD,
            nullptr, yh, yl, DD, DD, 0, 0, 0, 1.f);
        gat_scores<<<NN, blk>>>(yh, yl, enc_asrc + i * 256, enc_adst + i * 256, ssrc, sdst, 4);
        gat_agg<4><<<NN, blk>>>(yh, yl, ssrc, sdst, idxb, enc_b + i * DD, xh, xl, nullptr, 1);
        xih = xh; xil = xl;
    }

    // ---- transformer bottleneck: 2 layers
    for (int i = 0; i < 2; i++) {
        // qkv = x @ wqkv^T + bqkv   (K = DD = 256)
        gemm_bf3<128, 0><<<dim3(6, 32), blk>>>(xh, xl, DD,
            wh + O_WQKV + i * 196608, wl + O_WQKV + i * 196608, DD,
            tr_bqkv + i * 768, qkvh, qkvl, 768, DD, 0, 0, 0, 1.f);
        // S_h = (Q_h @ K_h^T)/8, heads batched over z
        gemm_bf3<128, 0><<<dim3(32, 32, 4), blk>>>(qkvh, qkvl, 768,
            qkvh + 256, qkvl + 256, 768,
            nullptr, atth, attl, NN, 64, 64, 64, HS, 0.125f);
        softmax_rows<<<dim3(NN, 4), blk>>>(atth, attl);
        vt_k<<<dim3(NN / 32, 2, 4), tblk>>>(qkvh, qkvl, vth, vtl);
        // O_h = P_h @ V_h (B = V^T, k-major)
        gemm_bf3<64, 0><<<dim3(1, 32, 4), blk>>>(atth, attl, NN,
            vth, vtl, NN,
            nullptr, yh, yl, DD, NN, HS, 64L * NN, 64, 1.f);
        gemm_bf3<64, 0><<<dim3(4, 32), blk>>>(yh, yl, DD,
            wh + O_WO + i * 65536, wl + O_WO + i * 65536, DD,
            tr_bo + i * DD, th, tl, DD, DD, 0, 0, 0, 1.f);
        add_ln_kernel<<<NN, blk>>>(xh, xl, th, tl, ln1g + i * DD, ln1b + i * DD, xh, xl);
        gemm_bf3<128, 1><<<dim3(4, 32), blk>>>(xh, xl, DD,
            wh + O_W1 + i * 131072, wl + O_W1 + i * 131072, DD,
            tr_b1 + i * 512, ffh, ffl, 512, DD, 0, 0, 0, 1.f);
        gemm_bf3<64, 0><<<dim3(4, 32), blk>>>(ffh, ffl, 512,
            wh + O_W2 + i * 131072, wl + O_W2 + i * 131072, 512,
            tr_b2 + i * DD, th, tl, DD, 512, 0, 0, 0, 1.f);
        add_ln_kernel<<<NN, blk>>>(xh, xl, th, tl, ln2g + i * DD, ln2b + i * DD, xh, xl);
    }

    // ---- skip connection
    gemm_bf3<64, 0><<<dim3(4, 32), blk>>>(winh, winl, DD, wh + O_SKIP, wl + O_SKIP, DD,
        skip_b, th, tl, DD, DD, 0, 0, 0, 1.f);
    add_pair<<<NN, blk>>>(xh, xl, th, tl);

    // ---- decoder: 2x GAT(4 heads)+relu, then single-head GAT
    for (int i = 0; i < 2; i++) {
        gemm_bf3<64, 0><<<dim3(4, 32), blk>>>(xh, xl, DD,
            wh + O_DECW + i * 65536, wl + O_DECW + i * 65536, DD,
            nullptr, yh, yl, DD, DD, 0, 0, 0, 1.f);
        gat_scores<<<NN, blk>>>(yh, yl, dec_asrc + i * 256, dec_adst + i * 256, ssrc, sdst, 4);
        gat_agg<4><<<NN, blk>>>(yh, yl, ssrc, sdst, idxb, dec_b + i * DD, xh, xl, nullptr, 1);
    }
    gemm_bf3<64, 0><<<dim3(4, 32), blk>>>(xh, xl, DD, wh + O_DECL, wl + O_DECL, DD,
        nullptr, yh, yl, DD, DD, 0, 0, 0, 1.f);
    gat_scores<<<NN, blk>>>(yh, yl, dec_lasrc, dec_ladst, ssrc, sdst, 1);
    gat_agg<1><<<NN, blk>>>(yh, yl, ssrc, sdst, idxb, dec_lb, nullptr, nullptr, tb, 0);

    // ---- output: transpose to [256, 4096]
    transpose_kernel<<<dim3(8, 128), dim3(32, 8)>>>(tb, (float*)d_out);
}

// round 9
// speedup vs baseline: 2.0217x; 1.3401x over previous
#include <cuda_runtime.h>
#include <cuda_bf16.h>
#include <math.h>
#include <stdint.h>

typedef __nv_bfloat16 bf16;

#define NN 4096
#define DD 256

// ---------------- scratch (device globals; no allocation) ----------------
__device__ bf16 g_win_h[NN * DD], g_win_l[NN * DD];
__device__ bf16 g_h0_h[NN * DD],  g_h0_l[NN * DD];
__device__ bf16 g_x_h[NN * DD],   g_x_l[NN * DD];
__device__ bf16 g_y_h[NN * DD],   g_y_l[NN * DD];
__device__ bf16 g_t_h[NN * DD],   g_t_l[NN * DD];
__device__ bf16 g_qkv_h[NN * 768], g_qkv_l[NN * 768];
__device__ bf16 g_ff_h[NN * 512],  g_ff_l[NN * 512];
__device__ bf16 g_sim_h[(long)NN * NN], g_sim_l[(long)NN * NN];   // 32MB each
#define WPOOL 1572864
__device__ bf16 g_w_h[WPOOL], g_w_l[WPOOL];
__device__ float g_tb[NN * DD];
__device__ float g_ssrc[NN * 4], g_sdst[NN * 4];
__device__ int   g_idx[NN * 16];

// ---------------- helpers -------------------------------------------------
__device__ __forceinline__ void cp16(uint32_t dst, const void* src) {
    asm volatile("cp.async.cg.shared.global [%0], [%1], 16;" :: "r"(dst), "l"(src));
}
#define CP_COMMIT() asm volatile("cp.async.commit_group;")

__device__ __forceinline__ float rec(const bf16* H, const bf16* L, long i) {
    return __bfloat162float(H[i]) + __bfloat162float(L[i]);
}
__device__ __forceinline__ void split1(float v, bf16* H, bf16* L, long off) {
    bf16 h = __float2bfloat16(v);
    H[off] = h;
    L[off] = __float2bfloat16(v - __bfloat162float(h));
}
__device__ __forceinline__ uint32_t pk(bf16 a, bf16 b) {
    __nv_bfloat162 t = __halves2bfloat162(a, b);
    return *(uint32_t*)&t;
}
__device__ __forceinline__ void split2st(float v0, float v1, bf16* H, bf16* L, long off) {
    bf16 h0 = __float2bfloat16(v0), h1 = __float2bfloat16(v1);
    float r0 = v0 - __bfloat162float(h0), r1 = v1 - __bfloat162float(h1);
    *(uint32_t*)(H + off) = pk(h0, h1);
    *(uint32_t*)(L + off) = pk(__float2bfloat16(r0), __float2bfloat16(r1));
}
__device__ __forceinline__ void splitpk(float v0, float v1, uint32_t& hi, uint32_t& lo) {
    bf16 h0 = __float2bfloat16(v0), h1 = __float2bfloat16(v1);
    hi = pk(h0, h1);
    lo = pk(__float2bfloat16(v0 - __bfloat162float(h0)),
            __float2bfloat16(v1 - __bfloat162float(h1)));
}

#define MMA_BF16(c, a, b0, b1) \
    asm volatile("mma.sync.aligned.m16n8k16.row.col.f32.bf16.bf16.f32 " \
                 "{%0,%1,%2,%3},{%4,%5,%6,%7},{%8,%9},{%0,%1,%2,%3};" \
                 : "+f"((c)[0]), "+f"((c)[1]), "+f"((c)[2]), "+f"((c)[3]) \
                 : "r"((a)[0]), "r"((a)[1]), "r"((a)[2]), "r"((a)[3]), \
                   "r"(b0), "r"(b1))

#define LDSM4(r, addr) \
    asm volatile("ldmatrix.sync.aligned.m8n8.x4.shared.b16 {%0,%1,%2,%3}, [%4];" \
                 : "=r"((r)[0]), "=r"((r)[1]), "=r"((r)[2]), "=r"((r)[3]) \
                 : "r"(addr))

#define LDSM4T(r, addr) \
    asm volatile("ldmatrix.sync.aligned.m8n8.x4.trans.shared.b16 {%0,%1,%2,%3}, [%4];" \
                 : "=r"((r)[0]), "=r"((r)[1]), "=r"((r)[2]), "=r"((r)[3]) \
                 : "r"(addr))

// ---------------- split-bf16 3-product GEMM (both operands k-major) -------
template<int BN, int ACT>
__global__ void __launch_bounds__(256) gemm_bf3(
    const bf16* __restrict__ Ah, const bf16* __restrict__ Al, int lda,
    const bf16* __restrict__ Bh, const bf16* __restrict__ Bl, int ldb,
    const float* __restrict__ bias,
    bf16* __restrict__ Ch, bf16* __restrict__ Cl, int ldc,
    int K, long sAz, long sBz, long sCz, float alpha)
{
    constexpr int NI = BN / 32;
    __shared__ bf16 sAh[2][128 * 24], sAl[2][128 * 24];
    __shared__ bf16 sBh[2][BN * 24],  sBl[2][BN * 24];

    const int tid = threadIdx.x;
    const int warp = tid >> 5, lane = tid & 31;
    const int g = lane >> 2, tig = lane & 3;
    const int wm = warp & 1, wn = warp >> 1;
    const int wm0 = wm * 64, wn0 = wn * (BN / 4);
    const int bm = blockIdx.y * 128, bn = blockIdx.x * BN;
    const long z = blockIdx.z;
    Ah += z * sAz; Al += z * sAz;
    Bh += z * sBz; Bl += z * sBz;
    Ch += z * sCz; Cl += z * sCz;

    const uint32_t offA = (uint32_t)(((wm0 + (lane & 15)) * 24 + (lane >> 4) * 8) * 2);
    const uint32_t offB = (uint32_t)(((wn0 + ((lane >> 4) & 1) * 8 + (lane & 7)) * 24
                                      + ((lane >> 3) & 1) * 8) * 2);
    uint32_t bAh[2] = { (uint32_t)__cvta_generic_to_shared(&sAh[0][0]),
                        (uint32_t)__cvta_generic_to_shared(&sAh[1][0]) };
    uint32_t bAl[2] = { (uint32_t)__cvta_generic_to_shared(&sAl[0][0]),
                        (uint32_t)__cvta_generic_to_shared(&sAl[1][0]) };
    uint32_t bBh[2] = { (uint32_t)__cvta_generic_to_shared(&sBh[0][0]),
                        (uint32_t)__cvta_generic_to_shared(&sBh[1][0]) };
    uint32_t bBl[2] = { (uint32_t)__cvta_generic_to_shared(&sBl[0][0]),
                        (uint32_t)__cvta_generic_to_shared(&sBl[1][0]) };

    float acc[4][NI][4];
#pragma unroll
    for (int mi = 0; mi < 4; mi++)
#pragma unroll
        for (int ni = 0; ni < NI; ni++)
#pragma unroll
            for (int q = 0; q < 4; q++) acc[mi][ni][q] = 0.f;

    auto load_tile = [&](int t, int buf) {
        const int k0 = t * 16;
        {
            int row = tid >> 1, half = tid & 1;
            uint32_t off = (uint32_t)(row * 24 + half * 8) * 2;
            long src = (long)(bm + row) * lda + k0 + half * 8;
            cp16(bAh[buf] + off, Ah + src);
            cp16(bAl[buf] + off, Al + src);
        }
        if (BN == 128 || tid < BN * 2) {
            int row = tid >> 1, half = tid & 1;
            uint32_t off = (uint32_t)(row * 24 + half * 8) * 2;
            long src = (long)(bn + row) * ldb + k0 + half * 8;
            cp16(bBh[buf] + off, Bh + src);
            cp16(bBl[buf] + off, Bl + src);
        }
    };

    load_tile(0, 0);
    CP_COMMIT();
    const int nt = K / 16;

    for (int t = 0; t < nt; t++) {
        if (t + 1 < nt) {
            load_tile(t + 1, (t + 1) & 1);
            CP_COMMIT();
            asm volatile("cp.async.wait_group 1;");
        } else {
            asm volatile("cp.async.wait_group 0;");
        }
        __syncthreads();
        const int buf = t & 1;

        uint32_t fah[4][4], fal[4][4];
#pragma unroll
        for (int mi = 0; mi < 4; mi++) {
            LDSM4(fah[mi], bAh[buf] + offA + mi * 768);
            LDSM4(fal[mi], bAl[buf] + offA + mi * 768);
        }
        uint32_t bh[NI][2], bl[NI][2];
#pragma unroll
        for (int pi = 0; pi < NI / 2; pi++) {
            LDSM4(bh[2 * pi], bBh[buf] + offB + pi * 768);
            LDSM4(bl[2 * pi], bBl[buf] + offB + pi * 768);
        }
#pragma unroll
        for (int ni = 0; ni < NI; ni++) {
#pragma unroll
            for (int mi = 0; mi < 4; mi++) {
                MMA_BF16(acc[mi][ni], fah[mi], bh[ni][0], bh[ni][1]);
                MMA_BF16(acc[mi][ni], fal[mi], bh[ni][0], bh[ni][1]);
                MMA_BF16(acc[mi][ni], fah[mi], bl[ni][0], bl[ni][1]);
            }
        }
        __syncthreads();
    }

#pragma unroll
    for (int mi = 0; mi < 4; mi++) {
#pragma unroll
        for (int ni = 0; ni < NI; ni++) {
            int col = bn + wn0 + ni * 8 + tig * 2;
            float b0 = 0.f, b1 = 0.f;
            if (bias) { b0 = bias[col]; b1 = bias[col + 1]; }
#pragma unroll
            for (int h2 = 0; h2 < 2; h2++) {
                int row = bm + wm0 + mi * 16 + g + h2 * 8;
                float v0 = acc[mi][ni][h2 * 2 + 0] * alpha + b0;
                float v1 = acc[mi][ni][h2 * 2 + 1] * alpha + b1;
                if (ACT == 1) { v0 = fmaxf(v0, 0.f); v1 = fmaxf(v1, 0.f); }
                if (ACT == 2) { v0 = tanhf(v0); v1 = tanhf(v1); }
                split2st(v0, v1, Ch, Cl, (long)row * ldc + col);
            }
        }
    }
}

// ---------------- fused flash attention (bf3, dual-plane P) ---------------
// grid (32, 4): 128 q-rows per block, head = blockIdx.y. 8 warps * 16 rows.
__global__ void __launch_bounds__(256) flash_attn(
    const bf16* __restrict__ Qh, const bf16* __restrict__ Ql,
    bf16* __restrict__ Oh, bf16* __restrict__ Ol)
{
    __shared__ char smem[2 * 18432];   // Q staging, then KV double buffer
    const int tid = threadIdx.x, lane = tid & 31, w = tid >> 5;
    const int g = lane >> 2, tig = lane & 3;
    const int q0 = blockIdx.x * 128;
    const int h = blockIdx.y;
    const uint32_t sbase = (uint32_t)__cvta_generic_to_shared(smem);

    // ---- stage Q tile (128x64, dual plane, stride 72 elems = 144B)
#pragma unroll
    for (int c = tid; c < 1024; c += 256) {
        int row = c >> 3, off = (c & 7) * 8;
        long src = (long)(q0 + row) * 768 + h * 64 + off;
        cp16(sbase + row * 144 + off * 2, Qh + src);
        cp16(sbase + 18432 + row * 144 + off * 2, Ql + src);
    }
    CP_COMMIT();
    asm volatile("cp.async.wait_group 0;");
    __syncthreads();

    uint32_t fqh[4][4], fql[4][4];
    {
        uint32_t offQ = (uint32_t)(((w * 16 + (lane & 15)) * 72 + (lane >> 4) * 8) * 2);
#pragma unroll
        for (int j = 0; j < 4; j++) {
            LDSM4(fqh[j], sbase + offQ + j * 32);
            LDSM4(fql[j], sbase + 18432 + offQ + j * 32);
        }
    }
    __syncthreads();   // Q reads done; smem reused as K/V buffers

    // KV buffer layout per stage (18432B): kh 0 / kl 4608 / vh 9216 / vl 13824
    auto load_kv = [&](int t, int b) {
        uint32_t base = sbase + b * 18432;
        int row = tid >> 3, off = (tid & 7) * 8;
        long key = (long)t * 32 + row;
        long srcK = key * 768 + 256 + h * 64 + off;
        long srcV = key * 768 + 512 + h * 64 + off;
        uint32_t d = row * 144 + off * 2;
        cp16(base + d,         Qh + srcK);
        cp16(base + 4608 + d,  Ql + srcK);
        cp16(base + 9216 + d,  Qh + srcV);
        cp16(base + 13824 + d, Ql + srcV);
    };

    const uint32_t offK = (uint32_t)(((((lane >> 4) & 1) * 8 + (lane & 7)) * 72
                                      + ((lane >> 3) & 1) * 8) * 2);
    const uint32_t offV = (uint32_t)(((lane & 15) * 72 + (lane >> 4) * 8) * 2);

    float m0v = -1e30f, m1v = -1e30f, l0 = 0.f, l1 = 0.f;
    float o[8][4];
#pragma unroll
    for (int nd = 0; nd < 8; nd++)
#pragma unroll
        for (int q = 0; q < 4; q++) o[nd][q] = 0.f;

    load_kv(0, 0);
    CP_COMMIT();

    for (int t = 0; t < 128; t++) {
        if (t + 1 < 128) {
            load_kv(t + 1, (t + 1) & 1);
            CP_COMMIT();
            asm volatile("cp.async.wait_group 1;");
        } else {
            asm volatile("cp.async.wait_group 0;");
        }
        __syncthreads();
        const uint32_t kb = sbase + (t & 1) * 18432;

        // ---- S = (Q @ K^T) * 0.125 : 16 rows x 32 keys per warp
        float s[4][4];
#pragma unroll
        for (int ni = 0; ni < 4; ni++)
#pragma unroll
            for (int q = 0; q < 4; q++) s[ni][q] = 0.f;
#pragma unroll
        for (int j = 0; j < 4; j++) {
            uint32_t bh[4], bl[4];
            LDSM4(bh, kb + offK + j * 32);                 // keys 0-15
            LDSM4(bl, kb + 4608 + offK + j * 32);
            MMA_BF16(s[0], fqh[j], bh[0], bh[1]);
            MMA_BF16(s[0], fql[j], bh[0], bh[1]);
            MMA_BF16(s[0], fqh[j], bl[0], bl[1]);
            MMA_BF16(s[1], fqh[j], bh[2], bh[3]);
            MMA_BF16(s[1], fql[j], bh[2], bh[3]);
            MMA_BF16(s[1], fqh[j], bl[2], bl[3]);
            uint32_t ch[4], cl[4];
            LDSM4(ch, kb + offK + 2304 + j * 32);          // keys 16-31
            LDSM4(cl, kb + 4608 + offK + 2304 + j * 32);
            MMA_BF16(s[2], fqh[j], ch[0], ch[1]);
            MMA_BF16(s[2], fql[j], ch[0], ch[1]);
            MMA_BF16(s[2], fqh[j], cl[0], cl[1]);
            MMA_BF16(s[3], fqh[j], ch[2], ch[3]);
            MMA_BF16(s[3], fql[j], ch[2], ch[3]);
            MMA_BF16(s[3], fqh[j], cl[2], cl[3]);
        }
#pragma unroll
        for (int ni = 0; ni < 4; ni++)
#pragma unroll
            for (int q = 0; q < 4; q++) s[ni][q] *= 0.125f;

        // ---- online softmax (rows g and g+8; each row spread over 4 lanes)
        float ml0 = -1e30f, ml1 = -1e30f;
#pragma unroll
        for (int ni = 0; ni < 4; ni++) {
            ml0 = fmaxf(ml0, fmaxf(s[ni][0], s[ni][1]));
            ml1 = fmaxf(ml1, fmaxf(s[ni][2], s[ni][3]));
        }
        ml0 = fmaxf(ml0, __shfl_xor_sync(0xffffffffu, ml0, 1));
        ml0 = fmaxf(ml0, __shfl_xor_sync(0xffffffffu, ml0, 2));
        ml1 = fmaxf(ml1, __shfl_xor_sync(0xffffffffu, ml1, 1));
        ml1 = fmaxf(ml1, __shfl_xor_sync(0xffffffffu, ml1, 2));
        float mn0 = fmaxf(m0v, ml0), mn1 = fmaxf(m1v, ml1);
        float c0 = __expf(m0v - mn0), c1 = __expf(m1v - mn1);
        m0v = mn0; m1v = mn1;
        float rs0 = 0.f, rs1 = 0.f;
#pragma unroll
        for (int ni = 0; ni < 4; ni++) {
            s[ni][0] = __expf(s[ni][0] - mn0); rs0 += s[ni][0];
            s[ni][1] = __expf(s[ni][1] - mn0); rs0 += s[ni][1];
            s[ni][2] = __expf(s[ni][2] - mn1); rs1 += s[ni][2];
            s[ni][3] = __expf(s[ni][3] - mn1); rs1 += s[ni][3];
        }
        rs0 += __shfl_xor_sync(0xffffffffu, rs0, 1);
        rs0 += __shfl_xor_sync(0xffffffffu, rs0, 2);
        rs1 += __shfl_xor_sync(0xffffffffu, rs1, 1);
        rs1 += __shfl_xor_sync(0xffffffffu, rs1, 2);
        l0 = l0 * c0 + rs0;
        l1 = l1 * c1 + rs1;
#pragma unroll
        for (int nd = 0; nd < 8; nd++) {
            o[nd][0] *= c0; o[nd][1] *= c0;
            o[nd][2] *= c1; o[nd][3] *= c1;
        }

        // ---- O += P @ V  (P dual-plane from registers, V via ldmatrix.trans)
#pragma unroll
        for (int c = 0; c < 2; c++) {
            uint32_t ah[4], al[4];
            splitpk(s[2 * c][0],     s[2 * c][1],     ah[0], al[0]);
            splitpk(s[2 * c][2],     s[2 * c][3],     ah[1], al[1]);
            splitpk(s[2 * c + 1][0], s[2 * c + 1][1], ah[2], al[2]);
            splitpk(s[2 * c + 1][2], s[2 * c + 1][3], ah[3], al[3]);
#pragma unroll
            for (int gg = 0; gg < 4; gg++) {
                uint32_t vh4[4], vl4[4];
                LDSM4T(vh4, kb + 9216 + offV + c * 2304 + gg * 32);
                LDSM4T(vl4, kb + 13824 + offV + c * 2304 + gg * 32);
                MMA_BF16(o[2 * gg],     ah, vh4[0], vh4[1]);
                MMA_BF16(o[2 * gg],     al, vh4[0], vh4[1]);
                MMA_BF16(o[2 * gg],     ah, vl4[0], vl4[1]);
                MMA_BF16(o[2 * gg + 1], ah, vh4[2], vh4[3]);
                MMA_BF16(o[2 * gg + 1], al, vh4[2], vh4[3]);
                MMA_BF16(o[2 * gg + 1], ah, vl4[2], vl4[3]);
            }
        }
        __syncthreads();
    }

    // ---- normalize + store (dual-plane)
    float i0 = 1.f / l0, i1 = 1.f / l1;
#pragma unroll
    for (int nd = 0; nd < 8; nd++) {
        int col = h * 64 + nd * 8 + tig * 2;
        long r0 = (long)(q0 + w * 16 + g) * 256 + col;
        long r1 = (long)(q0 + w * 16 + g + 8) * 256 + col;
        split2st(o[nd][0] * i0, o[nd][1] * i0, Oh, Ol, r0);
        split2st(o[nd][2] * i1, o[nd][3] * i1, Oh, Ol, r1);
    }
}

// ---------------- conversions ---------------------------------------------
__global__ void conv_k(const float* __restrict__ in, bf16* __restrict__ oh,
                       bf16* __restrict__ ol, int n)
{
    int i = blockIdx.x * 256 + threadIdx.x;
    if (i < n) split1(in[i], oh, ol, i);
}

__global__ void convT_k(const float* __restrict__ in, bf16* __restrict__ oh,
                        bf16* __restrict__ ol, int K, int N)
{
    __shared__ float tile[32][33];
    const int k0 = blockIdx.y * 32, n0 = blockIdx.x * 32;
    const int tx = threadIdx.x, ty = threadIdx.y;
#pragma unroll
    for (int p = 0; p < 4; p++)
        tile[ty + p * 8][tx] = in[(long)(k0 + ty + p * 8) * N + n0 + tx];
    __syncthreads();
#pragma unroll
    for (int p = 0; p < 4; p++) {
        int n = n0 + ty + p * 8, k = k0 + tx;
        split1(tile[tx][ty + p * 8], oh, ol, (long)n * K + k);
    }
}

// ---------------- top-16 per row (relu + diag mask, lowest-index ties) ----
__global__ void __launch_bounds__(256) topk_kernel(const bf16* __restrict__ Sh,
                                                   const bf16* __restrict__ Sl,
                                                   int* __restrict__ idx)
{
    const int row = blockIdx.x, t = threadIdx.x;
    float lv[16];
#pragma unroll
    for (int i = 0; i < 16; i++) {
        int j = i * 256 + t;
        float v = fmaxf(rec(Sh, Sl, (long)row * NN + j), 0.f);
        if (j == row) v = -1e9f;
        lv[i] = v;
    }
    __shared__ float sv[256];
    __shared__ int   si[256];
    for (int r = 0; r < 16; r++) {
        float bv = -2e9f; int bi = 0;
#pragma unroll
        for (int i = 0; i < 16; i++) {
            if (lv[i] > bv) { bv = lv[i]; bi = i * 256 + t; }
        }
        sv[t] = bv; si[t] = bi;
        __syncthreads();
        for (int s = 128; s > 0; s >>= 1) {
            if (t < s) {
                if (sv[t + s] > sv[t] || (sv[t + s] == sv[t] && si[t + s] < si[t])) {
                    sv[t] = sv[t + s]; si[t] = si[t + s];
                }
            }
            __syncthreads();
        }
        int winj = si[0];
        if (t == 0) idx[row * 16 + r] = winj;
        if ((winj & 255) == t) lv[winj >> 8] = -2e9f;
        __syncthreads();
    }
}

// ---------------- GAT score precompute ------------------------------------
__global__ void __launch_bounds__(256) gat_scores(const bf16* __restrict__ hh,
                                                  const bf16* __restrict__ hl,
                                                  const float* __restrict__ a_s,
                                                  const float* __restrict__ a_d,
                                                  float* __restrict__ ssrc,
                                                  float* __restrict__ sdst,
                                                  int heads)
{
    const int n = blockIdx.x, t = threadIdx.x;
    float hv = rec(hh, hl, (long)n * 256 + t);
    float ps = hv * a_s[t];
    float pd = hv * a_d[t];
#pragma unroll
    for (int m = 16; m; m >>= 1) {
        ps += __shfl_xor_sync(0xffffffffu, ps, m);
        pd += __shfl_xor_sync(0xffffffffu, pd, m);
    }
    __shared__ float ws[8], wd[8];
    if ((t & 31) == 0) { ws[t >> 5] = ps; wd[t >> 5] = pd; }
    __syncthreads();
    if (t < heads) {
        int wph = 8 / heads;
        float s = 0.f, d = 0.f;
        for (int w = 0; w < wph; w++) { s += ws[t * wph + w]; d += wd[t * wph + w]; }
        ssrc[n * heads + t] = s;
        sdst[n * heads + t] = d;
    }
}

// ---------------- GAT aggregation (17 in-edges per dst) -------------------
template<int HEADS>
__global__ void __launch_bounds__(256) gat_agg(const bf16* __restrict__ hh,
                                               const bf16* __restrict__ hl,
                                               const float* __restrict__ ssrc,
                                               const float* __restrict__ sdst,
                                               const int* __restrict__ idx,
                                               const float* __restrict__ bias,
                                               bf16* __restrict__ oh,
                                               bf16* __restrict__ ol,
                                               float* __restrict__ o32,
                                               int do_relu)
{
    const int i = blockIdx.x, t = threadIdx.x;
    __shared__ int   s_src[17];
    __shared__ float s_e[HEADS * 17];
    __shared__ float s_a[HEADS * 17];
    if (t < 16) s_src[t] = idx[i * 16 + t];
    if (t == 16) s_src[16] = i;
    __syncthreads();
    if (t < HEADS * 17) {
        int hh2 = t / 17, j = t % 17;
        float e = ssrc[s_src[j] * HEADS + hh2] + sdst[i * HEADS + hh2];
        s_e[t] = e > 0.f ? e : 0.2f * e;
    }
    __syncthreads();
    if (t < HEADS) {
        float m = -1e30f;
        for (int j = 0; j < 17; j++) m = fmaxf(m, s_e[t * 17 + j]);
        float s = 0.f;
        for (int j = 0; j < 17; j++) {
            float p = __expf(s_e[t * 17 + j] - m);
            s_a[t * 17 + j] = p; s += p;
        }
        float inv = 1.f / s;
        for (int j = 0; j < 17; j++) s_a[t * 17 + j] *= inv;
    }
    __syncthreads();
    const int hd = t / (256 / HEADS);
    float acc = 0.f;
#pragma unroll
    for (int j = 0; j < 17; j++)
        acc = fmaf(s_a[hd * 17 + j], rec(hh, hl, (long)s_src[j] * 256 + t), acc);
    float o = acc + bias[t];
    if (do_relu) o = fmaxf(o, 0.f);
    if (oh) split1(o, oh, ol, (long)i * 256 + t);
    else    o32[(long)i * 256 + t] = o;
}

// ---------------- residual + LayerNorm, dual-plane ------------------------
__global__ void __launch_bounds__(256) add_ln_kernel(const bf16* __restrict__ xh,
                                                     const bf16* __restrict__ xl,
                                                     const bf16* __restrict__ th,
                                                     const bf16* __restrict__ tl,
                                                     const float* __restrict__ g,
                                                     const float* __restrict__ b,
                                                     bf16* __restrict__ oh,
                                                     bf16* __restrict__ ol)
{
    const int n = blockIdx.x, t = threadIdx.x;
    const long off = (long)n * 256 + t;
    float v = rec(xh, xl, off) + rec(th, tl, off);
    __shared__ float red[8];
    float s = v;
#pragma unroll
    for (int m = 16; m; m >>= 1) s += __shfl_xor_sync(0xffffffffu, s, m);
    if ((t & 31) == 0) red[t >> 5] = s;
    __syncthreads();
    float tot = 0.f;
#pragma unroll
    for (int w = 0; w < 8; w++) tot += red[w];
    float mu = tot * (1.f / 256.f);
    float d = v - mu;
    float sq = d * d;
#pragma unroll
    for (int m = 16; m; m >>= 1) sq += __shfl_xor_sync(0xffffffffu, sq, m);
    __syncthreads();
    if ((t & 31) == 0) red[t >> 5] = sq;
    __syncthreads();
    float tv = 0.f;
#pragma unroll
    for (int w = 0; w < 8; w++) tv += red[w];
    float var = tv * (1.f / 256.f);
    split1(d * rsqrtf(var + 1e-5f) * g[t] + b[t], oh, ol, off);
}

// ---------------- dual-plane elementwise add ------------------------------
__global__ void add_pair(bf16* __restrict__ xh, bf16* __restrict__ xl,
                         const bf16* __restrict__ th, const bf16* __restrict__ tl)
{
    long i = (long)blockIdx.x * 256 + threadIdx.x;
    split1(rec(xh, xl, i) + rec(th, tl, i), xh, xl, i);
}

// ---------------- transpose [4096,256] fp32 -> [256,4096] -----------------
__global__ void transpose_kernel(const float* __restrict__ in, float* __restrict__ out)
{
    __shared__ float tile[32][33];
    const int bx = blockIdx.x * 32, by = blockIdx.y * 32;
    const int tx = threadIdx.x, ty = threadIdx.y;
#pragma unroll
    for (int p = 0; p < 4; p++)
        tile[ty + p * 8][tx] = in[(long)(by + ty + p * 8) * 256 + bx + tx];
    __syncthreads();
#pragma unroll
    for (int p = 0; p < 4; p++)
        out[(long)(bx + ty + p * 8) * 4096 + by + tx] = tile[tx][ty + p * 8];
}

// ---------------- launch ---------------------------------------------------
extern "C" void kernel_launch(void* const* d_in, const int* in_sizes, int n_in,
                              void* d_out, int out_size)
{
    const float* window   = (const float*)d_in[0];
    const float* gl_w     = (const float*)d_in[1];
    const float* gl_b     = (const float*)d_in[2];
    const float* enc_W    = (const float*)d_in[3];
    const float* enc_asrc = (const float*)d_in[4];
    const float* enc_adst = (const float*)d_in[5];
    const float* enc_b    = (const float*)d_in[6];
    const float* tr_wqkv  = (const float*)d_in[7];
    const float* tr_bqkv  = (const float*)d_in[8];
    const float* tr_wo    = (const float*)d_in[9];
    const float* tr_bo    = (const float*)d_in[10];
    const float* ln1g     = (const float*)d_in[11];
    const float* ln1b     = (const float*)d_in[12];
    const float* tr_w1    = (const float*)d_in[13];
    const float* tr_b1    = (const float*)d_in[14];
    const float* tr_w2    = (const float*)d_in[15];
    const float* tr_b2    = (const float*)d_in[16];
    const float* ln2g     = (const float*)d_in[17];
    const float* ln2b     = (const float*)d_in[18];
    const float* skip_w   = (const float*)d_in[19];
    const float* skip_b   = (const float*)d_in[20];
    const float* dec_W    = (const float*)d_in[21];
    const float* dec_asrc = (const float*)d_in[22];
    const float* dec_adst = (const float*)d_in[23];
    const float* dec_b    = (const float*)d_in[24];
    const float* dec_lW   = (const float*)d_in[25];
    const float* dec_lasrc= (const float*)d_in[26];
    const float* dec_ladst= (const float*)d_in[27];
    const float* dec_lb   = (const float*)d_in[28];

    bf16 *winh, *winl, *h0h, *h0l, *xh, *xl, *yh, *yl, *th, *tl;
    bf16 *qkvh, *qkvl, *ffh, *ffl, *simh, *siml, *wh, *wl;
    float *tb, *ssrc, *sdst;
    int* idxb;
    cudaGetSymbolAddress((void**)&winh, g_win_h); cudaGetSymbolAddress((void**)&winl, g_win_l);
    cudaGetSymbolAddress((void**)&h0h,  g_h0_h);  cudaGetSymbolAddress((void**)&h0l,  g_h0_l);
    cudaGetSymbolAddress((void**)&xh,   g_x_h);   cudaGetSymbolAddress((void**)&xl,   g_x_l);
    cudaGetSymbolAddress((void**)&yh,   g_y_h);   cudaGetSymbolAddress((void**)&yl,   g_y_l);
    cudaGetSymbolAddress((void**)&th,   g_t_h);   cudaGetSymbolAddress((void**)&tl,   g_t_l);
    cudaGetSymbolAddress((void**)&qkvh, g_qkv_h); cudaGetSymbolAddress((void**)&qkvl, g_qkv_l);
    cudaGetSymbolAddress((void**)&ffh,  g_ff_h);  cudaGetSymbolAddress((void**)&ffl,  g_ff_l);
    cudaGetSymbolAddress((void**)&simh, g_sim_h); cudaGetSymbolAddress((void**)&siml, g_sim_l);
    cudaGetSymbolAddress((void**)&wh,   g_w_h);   cudaGetSymbolAddress((void**)&wl,   g_w_l);
    cudaGetSymbolAddress((void**)&tb,   g_tb);
    cudaGetSymbolAddress((void**)&ssrc, g_ssrc);  cudaGetSymbolAddress((void**)&sdst, g_sdst);
    cudaGetSymbolAddress((void**)&idxb, g_idx);

    const long O_GLW = 0,       O_ENCW = 65536,  O_WQKV = 262144, O_WO = 655360;
    const long O_W1 = 786432,   O_W2 = 1048576,  O_SKIP = 1310720;
    const long O_DECW = 1376256, O_DECL = 1507328;

    dim3 blk(256), tblk(32, 8);

    // ---- input + weight conversion to dual-plane bf16 ----
    conv_k<<<NN * DD / 256, blk>>>(window, winh, winl, NN * DD);
    convT_k<<<dim3(8, 8), tblk>>>(gl_w, wh + O_GLW, wl + O_GLW, 256, 256);
    for (int i = 0; i < 3; i++)
        convT_k<<<dim3(8, 8), tblk>>>(enc_W + (long)i * 65536, wh + O_ENCW + i * 65536,
                                      wl + O_ENCW + i * 65536, 256, 256);
    for (int i = 0; i < 2; i++) {
        conv_k<<<768, blk>>>(tr_wqkv + (long)i * 196608, wh + O_WQKV + i * 196608,
                             wl + O_WQKV + i * 196608, 196608);
        conv_k<<<256, blk>>>(tr_wo + (long)i * 65536, wh + O_WO + i * 65536,
                             wl + O_WO + i * 65536, 65536);
        convT_k<<<dim3(16, 8), tblk>>>(tr_w1 + (long)i * 131072, wh + O_W1 + i * 131072,
                                       wl + O_W1 + i * 131072, 256, 512);
        convT_k<<<dim3(8, 16), tblk>>>(tr_w2 + (long)i * 131072, wh + O_W2 + i * 131072,
                                       wl + O_W2 + i * 131072, 512, 256);
        convT_k<<<dim3(8, 8), tblk>>>(dec_W + (long)i * 65536, wh + O_DECW + i * 65536,
                                      wl + O_DECW + i * 65536, 256, 256);
    }
    convT_k<<<dim3(8, 8), tblk>>>(skip_w, wh + O_SKIP, wl + O_SKIP, 256, 256);
    convT_k<<<dim3(8, 8), tblk>>>(dec_lW, wh + O_DECL, wl + O_DECL, 256, 256);

    // ---- graph learning: h0 = tanh(win @ glW + b); sim = h0 @ h0^T; top-16
    gemm_bf3<64, 2><<<dim3(4, 32), blk>>>(winh, winl, DD, wh + O_GLW, wl + O_GLW, DD,
        gl_b, h0h, h0l, DD, DD, 0, 0, 0, 1.f);
    gemm_bf3<128, 0><<<dim3(32, 32), blk>>>(h0h, h0l, DD, h0h, h0l, DD,
        nullptr, simh, siml, NN, DD, 0, 0, 0, 1.f);
    topk_kernel<<<NN, blk>>>(simh, siml, idxb);

    // ---- encoder: 3x GAT(4 heads) + relu
    const bf16* xih = winh; const bf16* xil = winl;
    for (int i = 0; i < 3; i++) {
        gemm_bf3<64, 0><<<dim3(4, 32), blk>>>(xih, xil, DD,
            wh + O_ENCW + i * 65536, wl + O_ENCW + i * 65536, DD,
            nullptr, yh, yl, DD, DD, 0, 0, 0, 1.f);
        gat_scores<<<NN, blk>>>(yh, yl, enc_asrc + i * 256, enc_adst + i * 256, ssrc, sdst, 4);
        gat_agg<4><<<NN, blk>>>(yh, yl, ssrc, sdst, idxb, enc_b + i * DD, xh, xl, nullptr, 1);
        xih = xh; xil = xl;
    }

    // ---- transformer bottleneck: 2 layers (fused flash attention)
    for (int i = 0; i < 2; i++) {
        gemm_bf3<128, 0><<<dim3(6, 32), blk>>>(xh, xl, DD,
            wh + O_WQKV + i * 196608, wl + O_WQKV + i * 196608, DD,
            tr_bqkv + i * 768, qkvh, qkvl, 768, DD, 0, 0, 0, 1.f);
        flash_attn<<<dim3(32, 4), blk>>>(qkvh, qkvl, yh, yl);
        gemm_bf3<64, 0><<<dim3(4, 32), blk>>>(yh, yl, DD,
            wh + O_WO + i * 65536, wl + O_WO + i * 65536, DD,
            tr_bo + i * DD, th, tl, DD, DD, 0, 0, 0, 1.f);
        add_ln_kernel<<<NN, blk>>>(xh, xl, th, tl, ln1g + i * DD, ln1b + i * DD, xh, xl);
        gemm_bf3<128, 1><<<dim3(4, 32), blk>>>(xh, xl, DD,
            wh + O_W1 + i * 131072, wl + O_W1 + i * 131072, DD,
            tr_b1 + i * 512, ffh, ffl, 512, DD, 0, 0, 0, 1.f);
        gemm_bf3<64, 0><<<dim3(4, 32), blk>>>(ffh, ffl, 512,
            wh + O_W2 + i * 131072, wl + O_W2 + i * 131072, 512,
            tr_b2 + i * DD, th, tl, DD, 512, 0, 0, 0, 1.f);
        add_ln_kernel<<<NN, blk>>>(xh, xl, th, tl, ln2g + i * DD, ln2b + i * DD, xh, xl);
    }

    // ---- skip connection
    gemm_bf3<64, 0><<<dim3(4, 32), blk>>>(winh, winl, DD, wh + O_SKIP, wl + O_SKIP, DD,
        skip_b, th, tl, DD, DD, 0, 0, 0, 1.f);
    add_pair<<<NN, blk>>>(xh, xl, th, tl);

    // ---- decoder: 2x GAT(4 heads)+relu, then single-head GAT
    for (int i = 0; i < 2; i++) {
        gemm_bf3<64, 0><<<dim3(4, 32), blk>>>(xh, xl, DD,
            wh + O_DECW + i * 65536, wl + O_DECW + i * 65536, DD,
            nullptr, yh, yl, DD, DD, 0, 0, 0, 1.f);
        gat_scores<<<NN, blk>>>(yh, yl, dec_asrc + i * 256, dec_adst + i * 256, ssrc, sdst, 4);
        gat_agg<4><<<NN, blk>>>(yh, yl, ssrc, sdst, idxb, dec_b + i * DD, xh, xl, nullptr, 1);
    }
    gemm_bf3<64, 0><<<dim3(4, 32), blk>>>(xh, xl, DD, wh + O_DECL, wl + O_DECL, DD,
        nullptr, yh, yl, DD, DD, 0, 0, 0, 1.f);
    gat_scores<<<NN, blk>>>(yh, yl, dec_lasrc, dec_ladst, ssrc, sdst, 1);
    gat_agg<1><<<NN, blk>>>(yh, yl, ssrc, sdst, idxb, dec_lb, nullptr, nullptr, tb, 0);

    // ---- output: transpose to [256, 4096]
    transpose_kernel<<<dim3(8, 128), dim3(32, 8)>>>(tb, (float*)d_out);
}